// round 1
// baseline (speedup 1.0000x reference)
#include <cuda_runtime.h>
#include <math.h>

// Problem dims
#define R_TOT 131072   // BS*N*G rows
#define TOKS  2048     // BS*N tokens

// Output layout: concatenation of flattened reference outputs, in order.
__device__ const size_t OFF_XOUT = 0;
__device__ const size_t OFF_Z    = 16777216;
__device__ const size_t OFF_ZH   = 25165824;
__device__ const size_t OFF_S    = 33554432;
__device__ const size_t OFF_KC   = 33685504;
__device__ const size_t OFF_VP   = 50462720;
__device__ const size_t OFF_G    = 67239936;
__device__ const size_t OFF_QN   = 67371008;
__device__ const size_t OFF_VC   = 84148224;
__device__ const size_t OFF_WN   = 100925440;

// Scratch (device globals: allocation-free)
__device__ float g_q [16777216];
__device__ float g_k [16777216];
__device__ float g_v [16777216];
__device__ float g_o [16777216];
__device__ float g_xa[16777216];   // attention-updated x_col
__device__ float g_hh[16777216];   // GLN(x)*gain  (MLP input)

// ---------------------------------------------------------------------------
// 8x8 and 8x4 register-tile FMA helpers. A is stored transposed in smem:
// As[k*lda + row]. B is natural: Bs[k*ldb + col]. Rows/cols split 0..63/64..127.
// ---------------------------------------------------------------------------
__device__ __forceinline__ void fma8x8(float acc[8][8], const float* As,
                                       const float* Bs, int lda, int ldb,
                                       int K, int tx, int ty) {
#pragma unroll 4
    for (int k = 0; k < K; k++) {
        float4 a0 = *(const float4*)(As + k * lda + ty * 4);
        float4 a1 = *(const float4*)(As + k * lda + 64 + ty * 4);
        float4 b0 = *(const float4*)(Bs + k * ldb + tx * 4);
        float4 b1 = *(const float4*)(Bs + k * ldb + 64 + tx * 4);
        float a[8] = {a0.x, a0.y, a0.z, a0.w, a1.x, a1.y, a1.z, a1.w};
        float b[8] = {b0.x, b0.y, b0.z, b0.w, b1.x, b1.y, b1.z, b1.w};
#pragma unroll
        for (int i = 0; i < 8; i++)
#pragma unroll
            for (int j = 0; j < 8; j++)
                acc[i][j] = fmaf(a[i], b[j], acc[i][j]);
    }
}

__device__ __forceinline__ void fma8x4(float acc[8][4], const float* As,
                                       const float* Bs, int lda, int ldb,
                                       int K, int tx, int ty) {
#pragma unroll 4
    for (int k = 0; k < K; k++) {
        float4 a0 = *(const float4*)(As + k * lda + ty * 4);
        float4 a1 = *(const float4*)(As + k * lda + 64 + ty * 4);
        float4 b0 = *(const float4*)(Bs + k * ldb + tx * 4);
        float a[8] = {a0.x, a0.y, a0.z, a0.w, a1.x, a1.y, a1.z, a1.w};
        float b[4] = {b0.x, b0.y, b0.z, b0.w};
#pragma unroll
        for (int i = 0; i < 8; i++)
#pragma unroll
            for (int j = 0; j < 4; j++)
                acc[i][j] = fmaf(a[i], b[j], acc[i][j]);
    }
}

__device__ __forceinline__ int rowOf(int ty, int i) { return (i < 4) ? ty * 4 + i : 64 + ty * 4 + (i - 4); }
__device__ __forceinline__ int colOf(int tx, int j) { return (j < 4) ? tx * 4 + j : 64 + tx * 4 + (j - 4); }

// ---------------------------------------------------------------------------
// K1: fused LayerNorm (lat_g/lat_b) + QKV projection.
// grid (R/128, 3): blockIdx.y selects {q,k,v}. 256 threads, 128x128x128 GEMM.
// ---------------------------------------------------------------------------
__global__ __launch_bounds__(256, 1)
void k_qkv(const float* __restrict__ x,
           const float* __restrict__ latg, const float* __restrict__ latb,
           const float* __restrict__ wq, const float* __restrict__ bq,
           const float* __restrict__ wk, const float* __restrict__ bk,
           const float* __restrict__ wv, const float* __restrict__ bv) {
    extern __shared__ float sm[];
    float* As = sm;                 // [128][132]  h (x after LN), transposed
    float* Bs = As + 128 * 132;     // [128][132]  weight
    float* mu = Bs + 128 * 132;     // [128]
    float* rs = mu + 128;           // [128]
    const int tid = threadIdx.x;
    const size_t rowbase = (size_t)blockIdx.x * 128;

    for (int i = tid; i < 128 * 128; i += 256) {
        int row = i >> 7, d = i & 127;
        As[d * 132 + row] = x[(rowbase + row) * 128 + d];
    }
    __syncthreads();
    if (tid < 128) {
        float s = 0.f;
        for (int k = 0; k < 128; k++) s += As[k * 132 + tid];
        float m = s * (1.0f / 128.0f);
        float v = 0.f;
        for (int k = 0; k < 128; k++) { float t = As[k * 132 + tid] - m; v += t * t; }
        mu[tid] = m;
        rs[tid] = rsqrtf(v * (1.0f / 128.0f) + 1e-5f);
    }
    __syncthreads();
    {   // apply LN in place (each thread: one row, half the channels)
        int row = tid & 127;
        int kh = tid >> 7;
        float m = mu[row], r = rs[row];
        for (int k = kh * 64; k < kh * 64 + 64; k++)
            As[k * 132 + row] = (As[k * 132 + row] - m) * r * latg[k] + latb[k];
    }
    const float* W; const float* bias; float* outp;
    if (blockIdx.y == 0)      { W = wq; bias = bq; outp = g_q; }
    else if (blockIdx.y == 1) { W = wk; bias = bk; outp = g_k; }
    else                      { W = wv; bias = bv; outp = g_v; }
    for (int i = tid; i < 128 * 128; i += 256) {
        int k = i >> 7, n = i & 127;
        Bs[k * 132 + n] = W[i];
    }
    __syncthreads();

    const int tx = tid & 15, ty = tid >> 4;
    float acc[8][8];
#pragma unroll
    for (int i = 0; i < 8; i++)
#pragma unroll
        for (int j = 0; j < 8; j++) acc[i][j] = 0.f;
    fma8x8(acc, As, Bs, 132, 132, 128, tx, ty);

    float bc[8];
#pragma unroll
    for (int j = 0; j < 8; j++) bc[j] = bias[colOf(tx, j)];
#pragma unroll
    for (int i = 0; i < 8; i++) {
        int row = rowOf(ty, i);
        size_t base = (rowbase + row) * 128;
        float4 v0 = make_float4(acc[i][0] + bc[0], acc[i][1] + bc[1], acc[i][2] + bc[2], acc[i][3] + bc[3]);
        float4 v1 = make_float4(acc[i][4] + bc[4], acc[i][5] + bc[5], acc[i][6] + bc[6], acc[i][7] + bc[7]);
        *(float4*)&outp[base + tx * 4]      = v0;
        *(float4*)&outp[base + 64 + tx * 4] = v1;
    }
}

// ---------------------------------------------------------------------------
// K2: attention over c=8 within each (s,n,b). rows contiguous (8 per block).
// ---------------------------------------------------------------------------
__global__ __launch_bounds__(128)
void k_attn() {
    __shared__ float qs[8][128], ks[8][128], vs[8][128], sc[8][8];
    const int tid = threadIdx.x;
    const size_t base = (size_t)blockIdx.x * 1024;
    for (int i = tid; i < 1024; i += 128) {
        int c = i >> 7, d = i & 127;
        qs[c][d] = g_q[base + i];
        ks[c][d] = g_k[base + i];
        vs[c][d] = g_v[base + i];
    }
    __syncthreads();
    if (tid < 64) {
        int c = tid >> 3, e = tid & 7;
        float s = 0.f;
        for (int d = 0; d < 128; d++) s += qs[c][d] * ks[e][d];
        sc[c][e] = s * 0.088388347648318447f;  // 128^-0.5
    }
    __syncthreads();
    if (tid < 8) {
        float m = sc[tid][0];
#pragma unroll
        for (int e = 1; e < 8; e++) m = fmaxf(m, sc[tid][e]);
        float ex[8], ssum = 0.f;
#pragma unroll
        for (int e = 0; e < 8; e++) { ex[e] = expf(sc[tid][e] - m); ssum += ex[e]; }
        float inv = 1.0f / ssum;
#pragma unroll
        for (int e = 0; e < 8; e++) sc[tid][e] = ex[e] * inv;
    }
    __syncthreads();
    for (int i = tid * 8; i < tid * 8 + 8; i++) {
        int c = i >> 7, d = i & 127;
        float s = 0.f;
#pragma unroll
        for (int e = 0; e < 8; e++) s += sc[c][e] * vs[e][d];
        g_o[base + i] = s;
    }
}

// ---------------------------------------------------------------------------
// K3: x_attn = x_col + o @ wo + bo
// ---------------------------------------------------------------------------
__global__ __launch_bounds__(256, 1)
void k_wo(const float* __restrict__ x, const float* __restrict__ wo,
          const float* __restrict__ bo) {
    extern __shared__ float sm[];
    float* As = sm;              // o transposed
    float* Bs = As + 128 * 132;  // wo
    const int tid = threadIdx.x;
    const size_t rowbase = (size_t)blockIdx.x * 128;
    for (int i = tid; i < 128 * 128; i += 256) {
        int row = i >> 7, d = i & 127;
        As[d * 132 + row] = g_o[(rowbase + row) * 128 + d];
    }
    for (int i = tid; i < 128 * 128; i += 256) {
        int k = i >> 7, n = i & 127;
        Bs[k * 132 + n] = wo[i];
    }
    __syncthreads();
    const int tx = tid & 15, ty = tid >> 4;
    float acc[8][8];
#pragma unroll
    for (int i = 0; i < 8; i++)
#pragma unroll
        for (int j = 0; j < 8; j++) acc[i][j] = 0.f;
    fma8x8(acc, As, Bs, 132, 132, 128, tx, ty);
    float bc[8];
#pragma unroll
    for (int j = 0; j < 8; j++) bc[j] = bo[colOf(tx, j)];
#pragma unroll
    for (int i = 0; i < 8; i++) {
        int row = rowOf(ty, i);
        size_t base = (rowbase + row) * 128;
        float4 x0 = *(const float4*)&x[base + tx * 4];
        float4 x1 = *(const float4*)&x[base + 64 + tx * 4];
        float4 v0 = make_float4(x0.x + acc[i][0] + bc[0], x0.y + acc[i][1] + bc[1],
                                x0.z + acc[i][2] + bc[2], x0.w + acc[i][3] + bc[3]);
        float4 v1 = make_float4(x1.x + acc[i][4] + bc[4], x1.y + acc[i][5] + bc[5],
                                x1.z + acc[i][6] + bc[6], x1.w + acc[i][7] + bc[7]);
        *(float4*)&g_xa[base + tx * 4]      = v0;
        *(float4*)&g_xa[base + 64 + tx * 4] = v1;
    }
}

// ---------------------------------------------------------------------------
// K4: per-group: z/enc, surprise, gate, z_hat/pred, gain, GLN*gain -> g_hh
// grid (TOKS/128, G). 256 threads.
// ---------------------------------------------------------------------------
__global__ __launch_bounds__(256, 1)
void k_small(const float* __restrict__ zhp,
             const float* __restrict__ lng, const float* __restrict__ lnb,
             const float* __restrict__ encw, const float* __restrict__ encb,
             const float* __restrict__ predw, const float* __restrict__ predb,
             const float* __restrict__ gainw, const float* __restrict__ gainb,
             float* out) {
    extern __shared__ float sm[];
    float* As = sm;                 // [128][132] x_attn transposed
    float* Zs = As + 128 * 132;     // [64][132]  z transposed
    float* Ds = Zs + 64 * 132;      // [64][132]  delta transposed
    float* Wb = Ds + 64 * 132;      // up to 128*128 weight buffer
    float* mu = Wb + 128 * 128;     // [128]
    float* rs = mu + 128;           // [128]
    const int tid = threadIdx.x;
    const int g = blockIdx.y;
    const int p0 = blockIdx.x * 128;

    for (int i = tid; i < 128 * 128; i += 256) {
        int row = i >> 7, d = i & 127;
        As[d * 132 + row] = g_xa[((size_t)(p0 + row) * 64 + g) * 128 + d];
    }
    for (int i = tid; i < 128 * 64; i += 256) Wb[i] = encw[(size_t)g * 8192 + i];
    __syncthreads();
    if (tid < 128) {   // GLN row stats of x_attn
        float s = 0.f;
        for (int k = 0; k < 128; k++) s += As[k * 132 + tid];
        float m = s * (1.0f / 128.0f);
        float v = 0.f;
        for (int k = 0; k < 128; k++) { float t = As[k * 132 + tid] - m; v += t * t; }
        mu[tid] = m;
        rs[tid] = rsqrtf(v * (1.0f / 128.0f) + 1e-5f);
    }
    __syncthreads();

    const int tx = tid & 15, ty = tid >> 4;
    // GEMM1: z = x @ enc_w  (K=128, N=64)
    {
        float acc[8][4];
#pragma unroll
        for (int i = 0; i < 8; i++)
#pragma unroll
            for (int j = 0; j < 4; j++) acc[i][j] = 0.f;
        fma8x4(acc, As, Wb, 132, 64, 128, tx, ty);
#pragma unroll
        for (int i = 0; i < 8; i++) {
            int row = rowOf(ty, i);
            size_t r = (size_t)(p0 + row) * 64 + g;
#pragma unroll
            for (int j = 0; j < 4; j++) {
                int c = tx * 4 + j;
                float zv = acc[i][j] + encb[g * 64 + c];
                out[OFF_Z + r * 64 + c] = zv;
                Zs[c * 132 + row] = zv;
                float dl = zv - zhp[r * 64 + c];
                Ds[c * 132 + row] = dl;
            }
        }
    }
    __syncthreads();
    if (tid < 128) {   // surprise + gate
        float s = 0.f;
        for (int k = 0; k < 64; k++) { float t = Ds[k * 132 + tid]; s += t * t; }
        float sp = sqrtf(s);
        size_t r = (size_t)(p0 + tid) * 64 + g;
        out[OFF_S + r] = sp;
        out[OFF_G + r] = fminf(sp, 1.0f);   // clip(sp/1.0, 0, 1), sp >= 0
    }
    for (int i = tid; i < 64 * 64; i += 256) Wb[i] = predw[(size_t)g * 4096 + i];
    __syncthreads();
    // GEMM2: z_hat = z @ pred_w  (K=64, N=64)
    {
        float acc[8][4];
#pragma unroll
        for (int i = 0; i < 8; i++)
#pragma unroll
            for (int j = 0; j < 4; j++) acc[i][j] = 0.f;
        fma8x4(acc, Zs, Wb, 132, 64, 64, tx, ty);
#pragma unroll
        for (int i = 0; i < 8; i++) {
            int row = rowOf(ty, i);
            size_t r = (size_t)(p0 + row) * 64 + g;
#pragma unroll
            for (int j = 0; j < 4; j++) {
                int c = tx * 4 + j;
                out[OFF_ZH + r * 64 + c] = acc[i][j] + predb[g * 64 + c];
            }
        }
    }
    __syncthreads();
    for (int i = tid; i < 64 * 128; i += 256) Wb[i] = gainw[(size_t)g * 8192 + i];
    __syncthreads();
    // GEMM3: gain = 1 + 0.1*tanh(delta @ gain_w + gain_b); hh = GLN(x)*gain
    {
        float acc[8][8];
#pragma unroll
        for (int i = 0; i < 8; i++)
#pragma unroll
            for (int j = 0; j < 8; j++) acc[i][j] = 0.f;
        fma8x8(acc, Ds, Wb, 132, 128, 64, tx, ty);
#pragma unroll
        for (int i = 0; i < 8; i++) {
            int row = rowOf(ty, i);
            size_t r = (size_t)(p0 + row) * 64 + g;
            float m = mu[row], rr = rs[row];
#pragma unroll
            for (int j = 0; j < 8; j++) {
                int c = colOf(tx, j);
                float gn = 1.0f + 0.1f * tanhf(acc[i][j] + gainb[(size_t)g * 128 + c]);
                float xl = (As[c * 132 + row] - m) * rr * lng[(size_t)g * 128 + c]
                           + lnb[(size_t)g * 128 + c];
                g_hh[r * 128 + c] = xl * gn;
            }
        }
    }
}

// ---------------------------------------------------------------------------
// K5: MLP: x_out = x_attn + down(gelu(up(hh))). K-chunked (4x128) over H=512.
// ---------------------------------------------------------------------------
__global__ __launch_bounds__(256, 1)
void k_mlp(const float* __restrict__ upw, const float* __restrict__ upb,
           const float* __restrict__ dww, const float* __restrict__ dwb,
           float* out) {
    extern __shared__ float sm[];
    float* As = sm;                 // hh transposed [128][132]
    float* Wb = As + 128 * 132;     // weight chunk [128][132]
    float* Ut = Wb + 128 * 132;     // u chunk transposed [128][132]
    const int tid = threadIdx.x;
    const int g = blockIdx.y;
    const int p0 = blockIdx.x * 128;
    for (int i = tid; i < 128 * 128; i += 256) {
        int row = i >> 7, d = i & 127;
        As[d * 132 + row] = g_hh[((size_t)(p0 + row) * 64 + g) * 128 + d];
    }
    const int tx = tid & 15, ty = tid >> 4;
    float oacc[8][8];
#pragma unroll
    for (int i = 0; i < 8; i++)
#pragma unroll
        for (int j = 0; j < 8; j++) oacc[i][j] = 0.f;

    for (int ch = 0; ch < 4; ch++) {
        __syncthreads();
        for (int i = tid; i < 128 * 128; i += 256) {
            int k = i >> 7, n = i & 127;
            Wb[k * 132 + n] = upw[(size_t)g * 65536 + (size_t)k * 512 + ch * 128 + n];
        }
        __syncthreads();
        float uacc[8][8];
#pragma unroll
        for (int i = 0; i < 8; i++)
#pragma unroll
            for (int j = 0; j < 8; j++) uacc[i][j] = 0.f;
        fma8x8(uacc, As, Wb, 132, 132, 128, tx, ty);
#pragma unroll
        for (int i = 0; i < 8; i++) {
            int row = rowOf(ty, i);
#pragma unroll
            for (int j = 0; j < 8; j++) {
                int c = colOf(tx, j);
                float u = uacc[i][j] + upb[(size_t)g * 512 + ch * 128 + c];
                u = 0.5f * u * (1.0f + erff(u * 0.70710678118654752f));  // exact gelu
                Ut[c * 132 + row] = u;
            }
        }
        __syncthreads();
        for (int i = tid; i < 128 * 128; i += 256) {
            int k = i >> 7, n = i & 127;
            Wb[k * 132 + n] = dww[(size_t)g * 65536 + (size_t)(ch * 128 + k) * 128 + n];
        }
        __syncthreads();
        fma8x8(oacc, Ut, Wb, 132, 132, 128, tx, ty);
    }
#pragma unroll
    for (int i = 0; i < 8; i++) {
        int row = rowOf(ty, i);
        size_t r = (size_t)(p0 + row) * 64 + g;
#pragma unroll
        for (int j = 0; j < 8; j++) {
            int c = colOf(tx, j);
            out[OFF_XOUT + r * 128 + c] = g_xa[r * 128 + c] + oacc[i][j]
                                          + dwb[(size_t)g * 128 + c];
        }
    }
}

// ---------------------------------------------------------------------------
// K6: post projection (128 -> 513) + k_cand/q_nov normalization + w_nov.
// ---------------------------------------------------------------------------
__global__ __launch_bounds__(256, 1)
void k_post(const float* __restrict__ pw, const float* __restrict__ pb,
            float* out) {
    extern __shared__ float sm[];
    float* As = sm;                 // x_out transposed [128][132]
    float* Bs = As + 128 * 132;     // post_w chunk [128][132]
    float* Cb = Bs + 128 * 132;     // [128][129] row-major chunk for norms
    float* rn = Cb + 128 * 129;     // [128] inverse norms
    float* wc = rn + 128;           // [128] last weight column
    const int tid = threadIdx.x;
    const int g = blockIdx.y;
    const int p0 = blockIdx.x * 128;
    for (int i = tid; i < 128 * 128; i += 256) {
        int row = i >> 7, d = i & 127;
        As[d * 132 + row] = out[OFF_XOUT + ((size_t)(p0 + row) * 64 + g) * 128 + d];
    }
    if (tid < 128) wc[tid] = pw[(size_t)g * 65664 + (size_t)tid * 513 + 512];
    __syncthreads();
    if (tid < 128) {   // novelty logit -> w_nov
        float s = 0.f;
        for (int k = 0; k < 128; k++) s += As[k * 132 + tid] * wc[k];
        s += pb[(size_t)g * 513 + 512];
        size_t r = (size_t)(p0 + tid) * 64 + g;
        out[OFF_WN + r] = 1.0f / (1.0f + expf(-s));
    }
    const int tx = tid & 15, ty = tid >> 4;
    for (int ch = 0; ch < 4; ch++) {
        __syncthreads();
        for (int i = tid; i < 128 * 128; i += 256) {
            int k = i >> 7, n = i & 127;
            Bs[k * 132 + n] = pw[(size_t)g * 65664 + (size_t)k * 513 + ch * 128 + n];
        }
        __syncthreads();
        float acc[8][8];
#pragma unroll
        for (int i = 0; i < 8; i++)
#pragma unroll
            for (int j = 0; j < 8; j++) acc[i][j] = 0.f;
        fma8x8(acc, As, Bs, 132, 132, 128, tx, ty);
#pragma unroll
        for (int i = 0; i < 8; i++)
#pragma unroll
            for (int j = 0; j < 8; j++)
                acc[i][j] += pb[(size_t)g * 513 + ch * 128 + colOf(tx, j)];

        if (ch == 1 || ch == 3) {     // v_post / v_cand: direct write
            size_t off = (ch == 1) ? OFF_VP : OFF_VC;
#pragma unroll
            for (int i = 0; i < 8; i++) {
                int row = rowOf(ty, i);
                size_t base = off + ((size_t)(p0 + row) * 64 + g) * 128;
                float4 v0 = make_float4(acc[i][0], acc[i][1], acc[i][2], acc[i][3]);
                float4 v1 = make_float4(acc[i][4], acc[i][5], acc[i][6], acc[i][7]);
                *(float4*)&out[base + tx * 4]      = v0;
                *(float4*)&out[base + 64 + tx * 4] = v1;
            }
        } else {                      // k_cand / q_nov: row-normalize
#pragma unroll
            for (int i = 0; i < 8; i++) {
                int row = rowOf(ty, i);
#pragma unroll
                for (int j = 0; j < 8; j++) Cb[row * 129 + colOf(tx, j)] = acc[i][j];
            }
            __syncthreads();
            if (tid < 128) {
                float s = 0.f;
                for (int k = 0; k < 128; k++) { float t = Cb[tid * 129 + k]; s += t * t; }
                rn[tid] = 1.0f / fmaxf(sqrtf(s), 1e-6f);
            }
            __syncthreads();
            size_t off = (ch == 0) ? OFF_KC : OFF_QN;
#pragma unroll
            for (int i = 0; i < 8; i++) {
                int row = rowOf(ty, i);
                float sc = rn[row];
                size_t base = off + ((size_t)(p0 + row) * 64 + g) * 128;
                float4 v0 = make_float4(acc[i][0] * sc, acc[i][1] * sc, acc[i][2] * sc, acc[i][3] * sc);
                float4 v1 = make_float4(acc[i][4] * sc, acc[i][5] * sc, acc[i][6] * sc, acc[i][7] * sc);
                *(float4*)&out[base + tx * 4]      = v0;
                *(float4*)&out[base + 64 + tx * 4] = v1;
            }
        }
    }
}

// ---------------------------------------------------------------------------
extern "C" void kernel_launch(void* const* d_in, const int* in_sizes, int n_in,
                              void* d_out, int out_size) {
    const float* x_col  = (const float*)d_in[0];
    const float* zhp    = (const float*)d_in[1];
    const float* ln_g   = (const float*)d_in[2];
    const float* ln_b   = (const float*)d_in[3];
    const float* up_w   = (const float*)d_in[4];
    const float* up_b   = (const float*)d_in[5];
    const float* down_w = (const float*)d_in[6];
    const float* down_b = (const float*)d_in[7];
    const float* lat_g  = (const float*)d_in[8];
    const float* lat_b  = (const float*)d_in[9];
    const float* wq     = (const float*)d_in[10];
    const float* bq     = (const float*)d_in[11];
    const float* wk     = (const float*)d_in[12];
    const float* bk     = (const float*)d_in[13];
    const float* wv     = (const float*)d_in[14];
    const float* bv     = (const float*)d_in[15];
    const float* wo     = (const float*)d_in[16];
    const float* bo     = (const float*)d_in[17];
    const float* post_w = (const float*)d_in[18];
    const float* post_b = (const float*)d_in[19];
    const float* enc_w  = (const float*)d_in[20];
    const float* enc_b  = (const float*)d_in[21];
    const float* pred_w = (const float*)d_in[22];
    const float* pred_b = (const float*)d_in[23];
    const float* gain_w = (const float*)d_in[24];
    const float* gain_b = (const float*)d_in[25];
    float* out = (float*)d_out;

    const int smem_qkv   = (128 * 132 * 2 + 256) * 4;
    const int smem_wo    = (128 * 132 * 2) * 4;
    const int smem_small = (128 * 132 + 64 * 132 * 2 + 128 * 128 + 256) * 4;
    const int smem_mlp   = (128 * 132 * 3) * 4;
    const int smem_post  = (128 * 132 * 2 + 128 * 129 + 256) * 4;

    cudaFuncSetAttribute(k_qkv,   cudaFuncAttributeMaxDynamicSharedMemorySize, smem_qkv);
    cudaFuncSetAttribute(k_wo,    cudaFuncAttributeMaxDynamicSharedMemorySize, smem_wo);
    cudaFuncSetAttribute(k_small, cudaFuncAttributeMaxDynamicSharedMemorySize, smem_small);
    cudaFuncSetAttribute(k_mlp,   cudaFuncAttributeMaxDynamicSharedMemorySize, smem_mlp);
    cudaFuncSetAttribute(k_post,  cudaFuncAttributeMaxDynamicSharedMemorySize, smem_post);

    k_qkv<<<dim3(R_TOT / 128, 3), 256, smem_qkv>>>(x_col, lat_g, lat_b,
                                                   wq, bq, wk, bk, wv, bv);
    k_attn<<<R_TOT / 8, 128>>>();
    k_wo<<<R_TOT / 128, 256, smem_wo>>>(x_col, wo, bo);
    k_small<<<dim3(TOKS / 128, 64), 256, smem_small>>>(zhp, ln_g, ln_b,
                                                       enc_w, enc_b, pred_w, pred_b,
                                                       gain_w, gain_b, out);
    k_mlp<<<dim3(TOKS / 128, 64), 256, smem_mlp>>>(up_w, up_b, down_w, down_b, out);
    k_post<<<dim3(TOKS / 128, 64), 256, smem_post>>>(post_w, post_b, out);
}

// round 3
// speedup vs baseline: 1.5371x; 1.5371x over previous
#include <cuda_runtime.h>
#include <math.h>
#include <stdint.h>

// Problem dims
#define R_TOT 131072   // BS*N*G rows
#define TOKS  2048     // BS*N tokens

// Output layout offsets (element index into float out buffer)
static constexpr size_t OFF_XOUT = 0;
static constexpr size_t OFF_Z    = 16777216;
static constexpr size_t OFF_ZH   = 25165824;
static constexpr size_t OFF_S    = 33554432;
static constexpr size_t OFF_KC   = 33685504;
static constexpr size_t OFF_VP   = 50462720;
static constexpr size_t OFF_G    = 67239936;
static constexpr size_t OFF_QN   = 67371008;
static constexpr size_t OFF_VC   = 84148224;
static constexpr size_t OFF_WN   = 100925440;

// Scratch (device globals: allocation-free)
__device__ float g_q [16777216];
__device__ float g_k [16777216];
__device__ float g_v [16777216];
__device__ float g_o [16777216];
__device__ float g_xa[16777216];   // attention-updated x_col
__device__ float g_hh[16777216];   // GLN(x)*gain  (MLP input)

// ===========================================================================
// tf32 mma.sync helpers (generic sm_80+ path; compiles for compute_103)
// ===========================================================================
__device__ __forceinline__ uint32_t cvt_tf32(float f) {
    uint32_t r;
    asm("cvt.rna.tf32.f32 %0, %1;" : "=r"(r) : "f"(f));
    return r;
}
__device__ __forceinline__ void mma8(float* c, const uint32_t* a,
                                     uint32_t b0, uint32_t b1) {
    asm volatile(
        "mma.sync.aligned.m16n8k8.row.col.f32.tf32.tf32.f32 "
        "{%0,%1,%2,%3}, {%4,%5,%6,%7}, {%8,%9}, {%0,%1,%2,%3};"
        : "+f"(c[0]), "+f"(c[1]), "+f"(c[2]), "+f"(c[3])
        : "r"(a[0]), "r"(a[1]), "r"(a[2]), "r"(a[3]), "r"(b0), "r"(b1));
}

// Warp computes a 32x64 output tile: 2 m16 tiles x 8 n8 tiles.
// As: [m][k] lda=LDA (conflict-free a-frags for LDA%32==4)
// Bs: [k][n] ldb=LDB (conflict-free b-frags for LDB%32==8)
template<int LDA, int LDB>
__device__ __forceinline__ void gemm_32x64(float acc[2][8][4],
        const uint32_t* __restrict__ As, const uint32_t* __restrict__ Bs,
        int mbase, int nbase, int K, int q, int t) {
#pragma unroll 2
    for (int kb = 0; kb < K; kb += 8) {
        uint32_t a[2][4];
#pragma unroll
        for (int mi = 0; mi < 2; mi++) {
            const uint32_t* ap = As + (mbase + mi * 16 + q) * LDA + kb + t;
            a[mi][0] = ap[0];
            a[mi][1] = ap[8 * LDA];
            a[mi][2] = ap[4];
            a[mi][3] = ap[8 * LDA + 4];
        }
#pragma unroll
        for (int nt = 0; nt < 8; nt++) {
            const uint32_t* bp = Bs + (kb + t) * LDB + nbase + nt * 8 + q;
            uint32_t b0 = bp[0], b1 = bp[4 * LDB];
            mma8(acc[0][nt], a[0], b0, b1);
            mma8(acc[1][nt], a[1], b0, b1);
        }
    }
}

// Warp computes a 16xN tile (NT = N/8 n-tiles), rows mbase..mbase+15.
template<int LDA, int LDB, int NT>
__device__ __forceinline__ void gemm_16(float acc[NT][4],
        const uint32_t* __restrict__ As, const uint32_t* __restrict__ Bs,
        int mbase, int K, int q, int t) {
#pragma unroll 2
    for (int kb = 0; kb < K; kb += 8) {
        uint32_t a[4];
        const uint32_t* ap = As + (mbase + q) * LDA + kb + t;
        a[0] = ap[0];
        a[1] = ap[8 * LDA];
        a[2] = ap[4];
        a[3] = ap[8 * LDA + 4];
#pragma unroll
        for (int nt = 0; nt < NT; nt++) {
            const uint32_t* bp = Bs + (kb + t) * LDB + nt * 8 + q;
            mma8(acc[nt], a, bp[0], bp[4 * LDB]);
        }
    }
}

__device__ __forceinline__ void zero_acc(float* a, int n) {
#pragma unroll
    for (int i = 0; i < n; i++) a[i] = 0.f;
}

// ===========================================================================
// K1: LN(lat) + QKV projection.  grid (1024, 3), 256 thr.
// ===========================================================================
__global__ __launch_bounds__(256, 1)
void k_qkv_tc(const float* __restrict__ x,
              const float* __restrict__ latg, const float* __restrict__ latb,
              const float* __restrict__ wq, const float* __restrict__ bq,
              const float* __restrict__ wk, const float* __restrict__ bk,
              const float* __restrict__ wv, const float* __restrict__ bv) {
    extern __shared__ uint32_t sm[];
    uint32_t* As = sm;                 // 128*132
    uint32_t* Bs = As + 128 * 132;     // 128*136
    float* sg = (float*)(Bs + 128 * 136);
    float* sb = sg + 128;
    const int tid = threadIdx.x;
    const size_t rowbase = (size_t)blockIdx.x * 128;
    if (tid < 128) { sg[tid] = latg[tid]; sb[tid] = latb[tid]; }

    const int r = tid >> 1, h = tid & 1;
    const float* xr = x + (rowbase + r) * 128 + h * 64;
    uint32_t* ar = As + r * 132 + h * 64;
    float s = 0.f, s2 = 0.f;
    for (int j = 0; j < 64; j += 4) {
        float4 v = *(const float4*)&xr[j];
        s += v.x + v.y + v.z + v.w;
        s2 += v.x * v.x + v.y * v.y + v.z * v.z + v.w * v.w;
        ar[j]     = __float_as_uint(v.x);
        ar[j + 1] = __float_as_uint(v.y);
        ar[j + 2] = __float_as_uint(v.z);
        ar[j + 3] = __float_as_uint(v.w);
    }
    s  += __shfl_xor_sync(0xffffffffu, s, 1);
    s2 += __shfl_xor_sync(0xffffffffu, s2, 1);
    float mu = s * (1.f / 128.f);
    float rs = rsqrtf(s2 * (1.f / 128.f) - mu * mu + 1e-5f);
    __syncthreads();   // sg/sb visible
    for (int j = 0; j < 64; j++) {
        float v = __uint_as_float(ar[j]);
        ar[j] = cvt_tf32((v - mu) * rs * sg[h * 64 + j] + sb[h * 64 + j]);
    }
    const float *W, *bias; float* outp;
    if (blockIdx.y == 0)      { W = wq; bias = bq; outp = g_q; }
    else if (blockIdx.y == 1) { W = wk; bias = bk; outp = g_k; }
    else                      { W = wv; bias = bv; outp = g_v; }
    for (int i = tid; i < 16384; i += 256)
        Bs[(i >> 7) * 136 + (i & 127)] = cvt_tf32(W[i]);
    __syncthreads();

    const int w = tid >> 5, lane = tid & 31, q = lane >> 2, t = lane & 3;
    const int mbase = (w >> 1) * 32, nbase = (w & 1) * 64;
    float acc[2][8][4];
    zero_acc(&acc[0][0][0], 64);
    gemm_32x64<132, 136>(acc, As, Bs, mbase, nbase, 128, q, t);
#pragma unroll
    for (int mi = 0; mi < 2; mi++)
#pragma unroll
        for (int nt = 0; nt < 8; nt++) {
            int rr = mbase + mi * 16 + q, cc = nbase + nt * 8 + 2 * t;
            float b0 = bias[cc], b1 = bias[cc + 1];
            float2 v0 = make_float2(acc[mi][nt][0] + b0, acc[mi][nt][1] + b1);
            float2 v1 = make_float2(acc[mi][nt][2] + b0, acc[mi][nt][3] + b1);
            *(float2*)&outp[(rowbase + rr) * 128 + cc] = v0;
            *(float2*)&outp[(rowbase + rr + 8) * 128 + cc] = v1;
        }
}

// ===========================================================================
// K2: attention over c=8 within each (s,n,b).
// ===========================================================================
__global__ __launch_bounds__(128)
void k_attn() {
    __shared__ float qs[8][128], ks[8][128], vs[8][128], sc[8][8];
    const int tid = threadIdx.x;
    const size_t base = (size_t)blockIdx.x * 1024;
    for (int i = tid; i < 1024; i += 128) {
        int c = i >> 7, d = i & 127;
        qs[c][d] = g_q[base + i];
        ks[c][d] = g_k[base + i];
        vs[c][d] = g_v[base + i];
    }
    __syncthreads();
    if (tid < 64) {
        int c = tid >> 3, e = tid & 7;
        float s = 0.f;
        for (int d = 0; d < 128; d++) s += qs[c][d] * ks[e][d];
        sc[c][e] = s * 0.088388347648318447f;
    }
    __syncthreads();
    if (tid < 8) {
        float m = sc[tid][0];
#pragma unroll
        for (int e = 1; e < 8; e++) m = fmaxf(m, sc[tid][e]);
        float ex[8], ssum = 0.f;
#pragma unroll
        for (int e = 0; e < 8; e++) { ex[e] = expf(sc[tid][e] - m); ssum += ex[e]; }
        float inv = 1.0f / ssum;
#pragma unroll
        for (int e = 0; e < 8; e++) sc[tid][e] = ex[e] * inv;
    }
    __syncthreads();
    for (int i = tid * 8; i < tid * 8 + 8; i++) {
        int c = i >> 7, d = i & 127;
        float s = 0.f;
#pragma unroll
        for (int e = 0; e < 8; e++) s += sc[c][e] * vs[e][d];
        g_o[base + i] = s;
    }
}

// ===========================================================================
// K3: x_attn = x + o @ wo + bo.  grid 1024, 256 thr.
// ===========================================================================
__global__ __launch_bounds__(256, 1)
void k_wo_tc(const float* __restrict__ x, const float* __restrict__ wo,
             const float* __restrict__ bo) {
    extern __shared__ uint32_t sm[];
    uint32_t* As = sm;
    uint32_t* Bs = As + 128 * 132;
    const int tid = threadIdx.x;
    const size_t rowbase = (size_t)blockIdx.x * 128;
    for (int i = tid; i < 16384; i += 256)
        As[(i >> 7) * 132 + (i & 127)] = cvt_tf32(g_o[rowbase * 128 + i]);
    for (int i = tid; i < 16384; i += 256)
        Bs[(i >> 7) * 136 + (i & 127)] = cvt_tf32(wo[i]);
    __syncthreads();

    const int w = tid >> 5, lane = tid & 31, q = lane >> 2, t = lane & 3;
    const int mbase = (w >> 1) * 32, nbase = (w & 1) * 64;
    float acc[2][8][4];
    zero_acc(&acc[0][0][0], 64);
    gemm_32x64<132, 136>(acc, As, Bs, mbase, nbase, 128, q, t);
#pragma unroll
    for (int mi = 0; mi < 2; mi++)
#pragma unroll
        for (int nt = 0; nt < 8; nt++) {
            int rr = mbase + mi * 16 + q, cc = nbase + nt * 8 + 2 * t;
            float b0 = bo[cc], b1 = bo[cc + 1];
            size_t o0 = (rowbase + rr) * 128 + cc;
            size_t o1 = (rowbase + rr + 8) * 128 + cc;
            float2 x0 = *(const float2*)&x[o0];
            float2 x1 = *(const float2*)&x[o1];
            *(float2*)&g_xa[o0] = make_float2(x0.x + acc[mi][nt][0] + b0,
                                              x0.y + acc[mi][nt][1] + b1);
            *(float2*)&g_xa[o1] = make_float2(x1.x + acc[mi][nt][2] + b0,
                                              x1.y + acc[mi][nt][3] + b1);
        }
}

// ===========================================================================
// K4: per-group small stages: z/enc, surprise+gate, z_hat/pred, gain, GLN*gain
// grid (16, 64), 256 thr.
// ===========================================================================
__global__ __launch_bounds__(256, 1)
void k_small_tc(const float* __restrict__ zhp,
                const float* __restrict__ lng, const float* __restrict__ lnb,
                const float* __restrict__ encw, const float* __restrict__ encb,
                const float* __restrict__ predw, const float* __restrict__ predb,
                const float* __restrict__ gainw, const float* __restrict__ gainb,
                float* out) {
    extern __shared__ uint32_t sm[];
    uint32_t* As = sm;                  // [128][132] x_attn (tf32)
    uint32_t* Zs = As + 128 * 132;      // [128][68]  z (tf32)
    uint32_t* Ds = Zs + 128 * 68;       // [128][68]  delta (tf32)
    uint32_t* Bs = Ds + 128 * 68;       // up to 128*72
    float* smu = (float*)(Bs + 128 * 72);
    float* srs = smu + 128;
    const int tid = threadIdx.x;
    const int g = blockIdx.y, p0 = blockIdx.x * 128;

    {   // load x_attn, single-pass stats, cvt store
        const int r = tid >> 1, h = tid & 1;
        const float* xr = g_xa + ((size_t)(p0 + r) * 64 + g) * 128 + h * 64;
        uint32_t* ar = As + r * 132 + h * 64;
        float s = 0.f, s2 = 0.f;
        for (int j = 0; j < 64; j += 4) {
            float4 v = *(const float4*)&xr[j];
            s += v.x + v.y + v.z + v.w;
            s2 += v.x * v.x + v.y * v.y + v.z * v.z + v.w * v.w;
            ar[j]     = cvt_tf32(v.x);
            ar[j + 1] = cvt_tf32(v.y);
            ar[j + 2] = cvt_tf32(v.z);
            ar[j + 3] = cvt_tf32(v.w);
        }
        s  += __shfl_xor_sync(0xffffffffu, s, 1);
        s2 += __shfl_xor_sync(0xffffffffu, s2, 1);
        float mu = s * (1.f / 128.f);
        if (h == 0) {
            smu[r] = mu;
            srs[r] = rsqrtf(s2 * (1.f / 128.f) - mu * mu + 1e-5f);
        }
    }
    for (int i = tid; i < 8192; i += 256)
        Bs[(i >> 6) * 72 + (i & 63)] = cvt_tf32(encw[(size_t)g * 8192 + i]);
    __syncthreads();

    const int w = tid >> 5, lane = tid & 31, q = lane >> 2, t = lane & 3;
    const int mbase = w * 16;

    {   // enc GEMM: z = x @ enc_w  (K=128, N=64)
        float acc[8][4];
        zero_acc(&acc[0][0], 32);
        gemm_16<132, 72, 8>(acc, As, Bs, mbase, 128, q, t);
        float sl = 0.f, sh = 0.f;
#pragma unroll
        for (int nt = 0; nt < 8; nt++) {
            int cc = nt * 8 + 2 * t;
            int rlo = mbase + q, rhi = rlo + 8;
            float z0 = acc[nt][0] + encb[g * 64 + cc];
            float z1 = acc[nt][1] + encb[g * 64 + cc + 1];
            float z2 = acc[nt][2] + encb[g * 64 + cc];
            float z3 = acc[nt][3] + encb[g * 64 + cc + 1];
            size_t qlo = (size_t)(p0 + rlo) * 64 + g;
            size_t qhi = (size_t)(p0 + rhi) * 64 + g;
            *(float2*)&out[OFF_Z + qlo * 64 + cc] = make_float2(z0, z1);
            *(float2*)&out[OFF_Z + qhi * 64 + cc] = make_float2(z2, z3);
            float2 plo = *(const float2*)&zhp[qlo * 64 + cc];
            float2 phi = *(const float2*)&zhp[qhi * 64 + cc];
            float d0 = z0 - plo.x, d1 = z1 - plo.y;
            float d2 = z2 - phi.x, d3 = z3 - phi.y;
            Zs[rlo * 68 + cc]     = cvt_tf32(z0);
            Zs[rlo * 68 + cc + 1] = cvt_tf32(z1);
            Zs[rhi * 68 + cc]     = cvt_tf32(z2);
            Zs[rhi * 68 + cc + 1] = cvt_tf32(z3);
            Ds[rlo * 68 + cc]     = cvt_tf32(d0);
            Ds[rlo * 68 + cc + 1] = cvt_tf32(d1);
            Ds[rhi * 68 + cc]     = cvt_tf32(d2);
            Ds[rhi * 68 + cc + 1] = cvt_tf32(d3);
            sl += d0 * d0 + d1 * d1;
            sh += d2 * d2 + d3 * d3;
        }
        sl += __shfl_xor_sync(0xffffffffu, sl, 1);
        sl += __shfl_xor_sync(0xffffffffu, sl, 2);
        sh += __shfl_xor_sync(0xffffffffu, sh, 1);
        sh += __shfl_xor_sync(0xffffffffu, sh, 2);
        if (t == 0) {
            float splo = sqrtf(sl), sphi = sqrtf(sh);
            size_t qlo = (size_t)(p0 + mbase + q) * 64 + g;
            size_t qhi = (size_t)(p0 + mbase + q + 8) * 64 + g;
            out[OFF_S + qlo] = splo;
            out[OFF_G + qlo] = fminf(splo, 1.0f);
            out[OFF_S + qhi] = sphi;
            out[OFF_G + qhi] = fminf(sphi, 1.0f);
        }
    }
    __syncthreads();
    for (int i = tid; i < 4096; i += 256)
        Bs[(i >> 6) * 72 + (i & 63)] = cvt_tf32(predw[(size_t)g * 4096 + i]);
    __syncthreads();
    {   // pred GEMM: z_hat = z @ pred_w  (K=64, N=64)
        float acc[8][4];
        zero_acc(&acc[0][0], 32);
        gemm_16<68, 72, 8>(acc, Zs, Bs, mbase, 64, q, t);
#pragma unroll
        for (int nt = 0; nt < 8; nt++) {
            int cc = nt * 8 + 2 * t;
            size_t qlo = (size_t)(p0 + mbase + q) * 64 + g;
            size_t qhi = (size_t)(p0 + mbase + q + 8) * 64 + g;
            float b0 = predb[g * 64 + cc], b1 = predb[g * 64 + cc + 1];
            *(float2*)&out[OFF_ZH + qlo * 64 + cc] =
                make_float2(acc[nt][0] + b0, acc[nt][1] + b1);
            *(float2*)&out[OFF_ZH + qhi * 64 + cc] =
                make_float2(acc[nt][2] + b0, acc[nt][3] + b1);
        }
    }
    __syncthreads();
    for (int i = tid; i < 8192; i += 256)
        Bs[(i >> 7) * 136 + (i & 127)] = cvt_tf32(gainw[(size_t)g * 8192 + i]);
    __syncthreads();
    {   // gain GEMM (K=64, N=128) + GLN epilogue -> g_hh
        float acc[16][4];
        zero_acc(&acc[0][0], 64);
        gemm_16<68, 136, 16>(acc, Ds, Bs, mbase, 64, q, t);
        int rlo = mbase + q, rhi = rlo + 8;
        float mlo = smu[rlo], rslo = srs[rlo];
        float mhi = smu[rhi], rshi = srs[rhi];
#pragma unroll
        for (int nt = 0; nt < 16; nt++) {
            int cc = nt * 8 + 2 * t;
#pragma unroll
            for (int jj = 0; jj < 2; jj++) {
                int c = cc + jj;
                float lg = lng[(size_t)g * 128 + c], lb = lnb[(size_t)g * 128 + c];
                float gb = gainb[(size_t)g * 128 + c];
                float gn0 = 1.0f + 0.1f * tanhf(acc[nt][jj] + gb);
                float gn1 = 1.0f + 0.1f * tanhf(acc[nt][2 + jj] + gb);
                float x0 = __uint_as_float(As[rlo * 132 + c]);
                float x1 = __uint_as_float(As[rhi * 132 + c]);
                float h0 = ((x0 - mlo) * rslo * lg + lb) * gn0;
                float h1 = ((x1 - mhi) * rshi * lg + lb) * gn1;
                g_hh[((size_t)(p0 + rlo) * 64 + g) * 128 + c] = h0;
                g_hh[((size_t)(p0 + rhi) * 64 + g) * 128 + c] = h1;
            }
        }
    }
}

// ===========================================================================
// K5: MLP: x_out = x_attn + down(gelu(up(hh))).  grid (16, 64), 256 thr.
// ===========================================================================
__global__ __launch_bounds__(256, 1)
void k_mlp_tc(const float* __restrict__ upw, const float* __restrict__ upb,
              const float* __restrict__ dww, const float* __restrict__ dwb,
              float* out) {
    extern __shared__ uint32_t sm[];
    uint32_t* As = sm;                 // [128][132] hh
    uint32_t* Us = As + 128 * 132;     // [128][132] gelu(u)
    uint32_t* Bs = Us + 128 * 132;     // [128][136] weight chunk
    const int tid = threadIdx.x;
    const int g = blockIdx.y, p0 = blockIdx.x * 128;

    for (int i = tid; i < 16384; i += 256) {
        int m = i >> 7, k = i & 127;
        As[m * 132 + k] = cvt_tf32(g_hh[((size_t)(p0 + m) * 64 + g) * 128 + k]);
    }
    const int w = tid >> 5, lane = tid & 31, q = lane >> 2, t = lane & 3;
    const int mbase = (w >> 1) * 32, nbase = (w & 1) * 64;

    float oacc[2][8][4];
    zero_acc(&oacc[0][0][0], 64);

    for (int ch = 0; ch < 4; ch++) {
        __syncthreads();
        for (int i = tid; i < 16384; i += 256) {
            int k = i >> 7, n = i & 127;
            Bs[k * 136 + n] = cvt_tf32(upw[(size_t)g * 65536 + (size_t)k * 512 + ch * 128 + n]);
        }
        __syncthreads();
        float uacc[2][8][4];
        zero_acc(&uacc[0][0][0], 64);
        gemm_32x64<132, 136>(uacc, As, Bs, mbase, nbase, 128, q, t);
#pragma unroll
        for (int mi = 0; mi < 2; mi++)
#pragma unroll
            for (int nt = 0; nt < 8; nt++) {
                int rr = mbase + mi * 16 + q, cc = nbase + nt * 8 + 2 * t;
#pragma unroll
                for (int jj = 0; jj < 2; jj++) {
                    float u0 = uacc[mi][nt][jj]     + upb[(size_t)g * 512 + ch * 128 + cc + jj];
                    float u1 = uacc[mi][nt][2 + jj] + upb[(size_t)g * 512 + ch * 128 + cc + jj];
                    u0 = 0.5f * u0 * (1.0f + erff(u0 * 0.70710678118654752f));
                    u1 = 0.5f * u1 * (1.0f + erff(u1 * 0.70710678118654752f));
                    Us[rr * 132 + cc + jj]       = cvt_tf32(u0);
                    Us[(rr + 8) * 132 + cc + jj] = cvt_tf32(u1);
                }
            }
        __syncthreads();
        for (int i = tid; i < 16384; i += 256) {
            int k = i >> 7, n = i & 127;
            Bs[k * 136 + n] = cvt_tf32(dww[(size_t)g * 65536 + (size_t)(ch * 128 + k) * 128 + n]);
        }
        __syncthreads();
        gemm_32x64<132, 136>(oacc, Us, Bs, mbase, nbase, 128, q, t);
    }
#pragma unroll
    for (int mi = 0; mi < 2; mi++)
#pragma unroll
        for (int nt = 0; nt < 8; nt++) {
            int rr = mbase + mi * 16 + q, cc = nbase + nt * 8 + 2 * t;
            float b0 = dwb[(size_t)g * 128 + cc], b1 = dwb[(size_t)g * 128 + cc + 1];
            size_t o0 = ((size_t)(p0 + rr) * 64 + g) * 128 + cc;
            size_t o1 = ((size_t)(p0 + rr + 8) * 64 + g) * 128 + cc;
            float2 x0 = *(const float2*)&g_xa[o0];
            float2 x1 = *(const float2*)&g_xa[o1];
            *(float2*)&out[OFF_XOUT + o0] = make_float2(x0.x + oacc[mi][nt][0] + b0,
                                                        x0.y + oacc[mi][nt][1] + b1);
            *(float2*)&out[OFF_XOUT + o1] = make_float2(x1.x + oacc[mi][nt][2] + b0,
                                                        x1.y + oacc[mi][nt][3] + b1);
        }
}

// ===========================================================================
// K6: post projection (128 -> 513) + normalize + w_nov.  grid (16, 64).
// ===========================================================================
__global__ __launch_bounds__(256, 1)
void k_post_tc(const float* __restrict__ pw, const float* __restrict__ pb,
               float* out) {
    extern __shared__ uint32_t sm[];
    uint32_t* As = sm;                 // [128][132] x_out
    uint32_t* Bs = As + 128 * 132;     // [128][136] chunk
    float* pr = (float*)(Bs + 128 * 136);   // [2][128] norm partials
    float* wcs = pr + 256;                  // [128] last weight col
    const int tid = threadIdx.x;
    const int g = blockIdx.y, p0 = blockIdx.x * 128;

    for (int i = tid; i < 16384; i += 256) {
        int m = i >> 7, k = i & 127;
        As[m * 132 + k] = cvt_tf32(out[OFF_XOUT + ((size_t)(p0 + m) * 64 + g) * 128 + k]);
    }
    if (tid < 128) wcs[tid] = pw[(size_t)g * 65664 + (size_t)tid * 513 + 512];
    __syncthreads();
    if (tid < 128) {   // novelty -> w_nov
        float s = 0.f;
        for (int k = 0; k < 128; k++)
            s += __uint_as_float(As[tid * 132 + k]) * wcs[k];
        s += pb[(size_t)g * 513 + 512];
        out[OFF_WN + (size_t)(p0 + tid) * 64 + g] = 1.0f / (1.0f + expf(-s));
    }
    const int w = tid >> 5, lane = tid & 31, q = lane >> 2, t = lane & 3;
    const int mbase = (w >> 1) * 32, nbase = (w & 1) * 64, wc = w & 1;

    for (int ch = 0; ch < 4; ch++) {
        __syncthreads();
        for (int i = tid; i < 16384; i += 256) {
            int k = i >> 7, n = i & 127;
            Bs[k * 136 + n] = cvt_tf32(pw[(size_t)g * 65664 + (size_t)k * 513 + ch * 128 + n]);
        }
        __syncthreads();
        float acc[2][8][4];
        zero_acc(&acc[0][0][0], 64);
        gemm_32x64<132, 136>(acc, As, Bs, mbase, nbase, 128, q, t);
#pragma unroll
        for (int mi = 0; mi < 2; mi++)
#pragma unroll
            for (int nt = 0; nt < 8; nt++) {
                int cc = nbase + nt * 8 + 2 * t;
                acc[mi][nt][0] += pb[(size_t)g * 513 + ch * 128 + cc];
                acc[mi][nt][1] += pb[(size_t)g * 513 + ch * 128 + cc + 1];
                acc[mi][nt][2] += pb[(size_t)g * 513 + ch * 128 + cc];
                acc[mi][nt][3] += pb[(size_t)g * 513 + ch * 128 + cc + 1];
            }
        if (ch == 1 || ch == 3) {
            size_t off = (ch == 1) ? OFF_VP : OFF_VC;
#pragma unroll
            for (int mi = 0; mi < 2; mi++)
#pragma unroll
                for (int nt = 0; nt < 8; nt++) {
                    int rr = mbase + mi * 16 + q, cc = nbase + nt * 8 + 2 * t;
                    size_t o0 = off + ((size_t)(p0 + rr) * 64 + g) * 128 + cc;
                    size_t o1 = off + ((size_t)(p0 + rr + 8) * 64 + g) * 128 + cc;
                    *(float2*)&out[o0] = make_float2(acc[mi][nt][0], acc[mi][nt][1]);
                    *(float2*)&out[o1] = make_float2(acc[mi][nt][2], acc[mi][nt][3]);
                }
        } else {
            float sl[2] = {0.f, 0.f}, sh[2] = {0.f, 0.f};
#pragma unroll
            for (int mi = 0; mi < 2; mi++)
#pragma unroll
                for (int nt = 0; nt < 8; nt++) {
                    sl[mi] += acc[mi][nt][0] * acc[mi][nt][0] + acc[mi][nt][1] * acc[mi][nt][1];
                    sh[mi] += acc[mi][nt][2] * acc[mi][nt][2] + acc[mi][nt][3] * acc[mi][nt][3];
                }
#pragma unroll
            for (int mi = 0; mi < 2; mi++) {
                sl[mi] += __shfl_xor_sync(0xffffffffu, sl[mi], 1);
                sl[mi] += __shfl_xor_sync(0xffffffffu, sl[mi], 2);
                sh[mi] += __shfl_xor_sync(0xffffffffu, sh[mi], 1);
                sh[mi] += __shfl_xor_sync(0xffffffffu, sh[mi], 2);
            }
            if (t == 0) {
#pragma unroll
                for (int mi = 0; mi < 2; mi++) {
                    pr[wc * 128 + mbase + mi * 16 + q] = sl[mi];
                    pr[wc * 128 + mbase + mi * 16 + q + 8] = sh[mi];
                }
            }
            __syncthreads();
            size_t off = (ch == 0) ? OFF_KC : OFF_QN;
#pragma unroll
            for (int mi = 0; mi < 2; mi++)
#pragma unroll
                for (int nt = 0; nt < 8; nt++) {
                    int rr = mbase + mi * 16 + q, cc = nbase + nt * 8 + 2 * t;
                    float i0 = 1.0f / fmaxf(sqrtf(pr[rr] + pr[128 + rr]), 1e-6f);
                    float i1 = 1.0f / fmaxf(sqrtf(pr[rr + 8] + pr[128 + rr + 8]), 1e-6f);
                    size_t o0 = off + ((size_t)(p0 + rr) * 64 + g) * 128 + cc;
                    size_t o1 = off + ((size_t)(p0 + rr + 8) * 64 + g) * 128 + cc;
                    *(float2*)&out[o0] = make_float2(acc[mi][nt][0] * i0, acc[mi][nt][1] * i0);
                    *(float2*)&out[o1] = make_float2(acc[mi][nt][2] * i1, acc[mi][nt][3] * i1);
                }
        }
    }
}

// ===========================================================================
extern "C" void kernel_launch(void* const* d_in, const int* in_sizes, int n_in,
                              void* d_out, int out_size) {
    const float* x_col  = (const float*)d_in[0];
    const float* zhp    = (const float*)d_in[1];
    const float* ln_g   = (const float*)d_in[2];
    const float* ln_b   = (const float*)d_in[3];
    const float* up_w   = (const float*)d_in[4];
    const float* up_b   = (const float*)d_in[5];
    const float* down_w = (const float*)d_in[6];
    const float* down_b = (const float*)d_in[7];
    const float* lat_g  = (const float*)d_in[8];
    const float* lat_b  = (const float*)d_in[9];
    const float* wq     = (const float*)d_in[10];
    const float* bq     = (const float*)d_in[11];
    const float* wk     = (const float*)d_in[12];
    const float* bk     = (const float*)d_in[13];
    const float* wv     = (const float*)d_in[14];
    const float* bv     = (const float*)d_in[15];
    const float* wo     = (const float*)d_in[16];
    const float* bo     = (const float*)d_in[17];
    const float* post_w = (const float*)d_in[18];
    const float* post_b = (const float*)d_in[19];
    const float* enc_w  = (const float*)d_in[20];
    const float* enc_b  = (const float*)d_in[21];
    const float* pred_w = (const float*)d_in[22];
    const float* pred_b = (const float*)d_in[23];
    const float* gain_w = (const float*)d_in[24];
    const float* gain_b = (const float*)d_in[25];
    float* out = (float*)d_out;

    const int SM_QKV   = (128 * 132 + 128 * 136 + 256) * 4;
    const int SM_WO    = (128 * 132 + 128 * 136) * 4;
    const int SM_SMALL = (128 * 132 + 128 * 68 * 2 + 128 * 72 + 256) * 4;
    const int SM_MLP   = (128 * 132 * 2 + 128 * 136) * 4;
    const int SM_POST  = (128 * 132 + 128 * 136 + 384) * 4;

    cudaFuncSetAttribute(k_qkv_tc,   cudaFuncAttributeMaxDynamicSharedMemorySize, SM_QKV);
    cudaFuncSetAttribute(k_wo_tc,    cudaFuncAttributeMaxDynamicSharedMemorySize, SM_WO);
    cudaFuncSetAttribute(k_small_tc, cudaFuncAttributeMaxDynamicSharedMemorySize, SM_SMALL);
    cudaFuncSetAttribute(k_mlp_tc,   cudaFuncAttributeMaxDynamicSharedMemorySize, SM_MLP);
    cudaFuncSetAttribute(k_post_tc,  cudaFuncAttributeMaxDynamicSharedMemorySize, SM_POST);

    k_qkv_tc<<<dim3(R_TOT / 128, 3), 256, SM_QKV>>>(x_col, lat_g, lat_b,
                                                    wq, bq, wk, bk, wv, bv);
    k_attn<<<R_TOT / 8, 128>>>();
    k_wo_tc<<<R_TOT / 128, 256, SM_WO>>>(x_col, wo, bo);
    k_small_tc<<<dim3(TOKS / 128, 64), 256, SM_SMALL>>>(zhp, ln_g, ln_b,
                                                        enc_w, enc_b, pred_w, pred_b,
                                                        gain_w, gain_b, out);
    k_mlp_tc<<<dim3(TOKS / 128, 64), 256, SM_MLP>>>(up_w, up_b, down_w, down_b, out);
    k_post_tc<<<dim3(TOKS / 128, 64), 256, SM_POST>>>(post_w, post_b, out);
}

// round 4
// speedup vs baseline: 2.7902x; 1.8153x over previous
#include <cuda_runtime.h>
#include <math.h>
#include <stdint.h>

#define R_TOT 131072   // BS*N*G rows
#define TOKS  2048     // BS*N tokens

// Output layout offsets (element index into float out buffer)
static constexpr size_t OFF_XOUT = 0;
static constexpr size_t OFF_Z    = 16777216;
static constexpr size_t OFF_ZH   = 25165824;
static constexpr size_t OFF_S    = 33554432;
static constexpr size_t OFF_KC   = 33685504;
static constexpr size_t OFF_VP   = 50462720;
static constexpr size_t OFF_G    = 67239936;
static constexpr size_t OFF_QN   = 67371008;
static constexpr size_t OFF_VC   = 84148224;
static constexpr size_t OFF_WN   = 100925440;

// Scratch (device globals: allocation-free)
__device__ float g_q [16777216];
__device__ float g_k [16777216];
__device__ float g_v [16777216];
__device__ float g_o [16777216];
__device__ float g_xa[16777216];
__device__ float g_hh[16777216];

// Pre-converted tf32 weights
__device__ uint32_t gw_qkvo[65536];       // wq,wk,wv,wo @ 0,16384,32768,49152
__device__ uint32_t gw_enc [524288];      // [g][128][64]
__device__ uint32_t gw_pred[262144];      // [g][64][64]
__device__ uint32_t gw_gain[524288];      // [g][64][128]
__device__ uint32_t gw_up  [4194304];     // [g][8ch][128k][64n]
__device__ uint32_t gw_down[4194304];     // [g][512][128] (straight)
__device__ uint32_t gw_post[4194304];     // [g][4ch][128k][128n]
__device__ float    gw_plast[8192];       // post_w last column [g][128]

// ===========================================================================
// helpers
// ===========================================================================
__device__ __forceinline__ uint32_t cvt_tf32(float f) {
    uint32_t r;
    asm("cvt.rna.tf32.f32 %0, %1;" : "=r"(r) : "f"(f));
    return r;
}
__device__ __forceinline__ void mma8(float* c, const uint32_t* a,
                                     uint32_t b0, uint32_t b1) {
    asm volatile(
        "mma.sync.aligned.m16n8k8.row.col.f32.tf32.tf32.f32 "
        "{%0,%1,%2,%3}, {%4,%5,%6,%7}, {%8,%9}, {%0,%1,%2,%3};"
        : "+f"(c[0]), "+f"(c[1]), "+f"(c[2]), "+f"(c[3])
        : "r"(a[0]), "r"(a[1]), "r"(a[2]), "r"(a[3]), "r"(b0), "r"(b1));
}
__device__ __forceinline__ void cp16(void* smem, const void* gmem) {
    uint32_t s = (uint32_t)__cvta_generic_to_shared(smem);
    asm volatile("cp.async.cg.shared.global [%0], [%1], 16;" :: "r"(s), "l"(gmem));
}
__device__ __forceinline__ void cp_commit() {
    asm volatile("cp.async.commit_group;" ::: "memory");
}
template<int N> __device__ __forceinline__ void cp_wait() {
    asm volatile("cp.async.wait_group %0;" :: "n"(N) : "memory");
}
// copy ROWSx128 uint32 gmem tile -> smem (row stride 136)
__device__ __forceinline__ void cpy136(uint32_t* dst, const uint32_t* src,
                                       int rows, int tid) {
    for (int i = tid; i < rows * 32; i += 256) {
        int k = i >> 5, n = (i & 31) * 4;
        cp16(dst + k * 136 + n, src + k * 128 + n);
    }
}
// copy ROWSx64 uint32 gmem tile -> smem (row stride 72)
__device__ __forceinline__ void cpy72(uint32_t* dst, const uint32_t* src,
                                      int rows, int tid) {
    for (int i = tid; i < rows * 16; i += 256) {
        int k = i >> 4, n = (i & 15) * 4;
        cp16(dst + k * 72 + n, src + k * 64 + n);
    }
}

template<int LDA, int LDB>
__device__ __forceinline__ void gemm_32x64(float acc[2][8][4],
        const uint32_t* __restrict__ As, const uint32_t* __restrict__ Bs,
        int mbase, int nbase, int K, int q, int t) {
#pragma unroll 2
    for (int kb = 0; kb < K; kb += 8) {
        uint32_t a[2][4];
#pragma unroll
        for (int mi = 0; mi < 2; mi++) {
            const uint32_t* ap = As + (mbase + mi * 16 + q) * LDA + kb + t;
            a[mi][0] = ap[0];
            a[mi][1] = ap[8 * LDA];
            a[mi][2] = ap[4];
            a[mi][3] = ap[8 * LDA + 4];
        }
#pragma unroll
        for (int nt = 0; nt < 8; nt++) {
            const uint32_t* bp = Bs + (kb + t) * LDB + nbase + nt * 8 + q;
            uint32_t b0 = bp[0], b1 = bp[4 * LDB];
            mma8(acc[0][nt], a[0], b0, b1);
            mma8(acc[1][nt], a[1], b0, b1);
        }
    }
}
template<int LDA, int LDB, int NT>
__device__ __forceinline__ void gemm_16(float acc[NT][4],
        const uint32_t* __restrict__ As, const uint32_t* __restrict__ Bs,
        int mbase, int K, int q, int t) {
#pragma unroll 2
    for (int kb = 0; kb < K; kb += 8) {
        uint32_t a[4];
        const uint32_t* ap = As + (mbase + q) * LDA + kb + t;
        a[0] = ap[0];
        a[1] = ap[8 * LDA];
        a[2] = ap[4];
        a[3] = ap[8 * LDA + 4];
#pragma unroll
        for (int nt = 0; nt < NT; nt++) {
            const uint32_t* bp = Bs + (kb + t) * LDB + nt * 8 + q;
            mma8(acc[nt], a, bp[0], bp[4 * LDB]);
        }
    }
}
__device__ __forceinline__ void zero_acc(float* a, int n) {
#pragma unroll
    for (int i = 0; i < n; i++) a[i] = 0.f;
}

// ===========================================================================
// Weight preparation kernels
// ===========================================================================
__global__ void k_cvt_qkvo(const float* __restrict__ wq, const float* __restrict__ wk,
                           const float* __restrict__ wv, const float* __restrict__ wo) {
    int i = blockIdx.x * 256 + threadIdx.x, st = gridDim.x * 256;
    for (; i < 65536; i += st) {
        int sel = i >> 14, j = i & 16383;
        const float* p = (sel == 0) ? wq : (sel == 1) ? wk : (sel == 2) ? wv : wo;
        gw_qkvo[i] = cvt_tf32(p[j]);
    }
}
__global__ void k_cvt_small(const float* __restrict__ encw,
                            const float* __restrict__ predw,
                            const float* __restrict__ gainw) {
    int i = blockIdx.x * 256 + threadIdx.x, st = gridDim.x * 256;
    for (; i < 1310720; i += st) {
        if (i < 524288) gw_enc[i] = cvt_tf32(encw[i]);
        else if (i < 786432) gw_pred[i - 524288] = cvt_tf32(predw[i - 524288]);
        else gw_gain[i - 786432] = cvt_tf32(gainw[i - 786432]);
    }
}
__global__ void k_cvt_down(const float* __restrict__ dw) {
    int i = blockIdx.x * 256 + threadIdx.x, st = gridDim.x * 256;
    for (; i < 4194304; i += st) gw_down[i] = cvt_tf32(dw[i]);
}
__global__ void k_cvt_up(const float* __restrict__ uw) {
    int i = blockIdx.x * 256 + threadIdx.x, st = gridDim.x * 256;
    for (; i < 4194304; i += st) {
        int g = i >> 16, ch = (i >> 13) & 7, k = (i >> 6) & 127, n = i & 63;
        gw_up[i] = cvt_tf32(uw[(size_t)(g * 128 + k) * 512 + ch * 64 + n]);
    }
}
__global__ void k_cvt_post(const float* __restrict__ pw) {
    int i = blockIdx.x * 256 + threadIdx.x, st = gridDim.x * 256;
    for (; i < 4194304; i += st) {
        int g = i >> 16, ch = (i >> 14) & 3, k = (i >> 7) & 127, n = i & 127;
        gw_post[i] = cvt_tf32(pw[(size_t)(g * 128 + k) * 513 + ch * 128 + n]);
        if (i < 8192) {
            int gg = i >> 7, kk = i & 127;
            gw_plast[i] = pw[(size_t)(gg * 128 + kk) * 513 + 512];
        }
    }
}

// ===========================================================================
// K1: LN(lat) + merged QKV.  grid 1024, 256 thr.
// smem: As[128*132] + B0/B1[128*136] + 256 stats
// ===========================================================================
__device__ __forceinline__ void qkv_gemm_epi(const uint32_t* As, const uint32_t* Bs,
        const float* __restrict__ bias, float* __restrict__ outp,
        size_t rowbase, int w, int q, int t) {
    const int mbase = (w >> 1) * 32, nbase = (w & 1) * 64;
    float acc[2][8][4];
    zero_acc(&acc[0][0][0], 64);
    gemm_32x64<132, 136>(acc, As, Bs, mbase, nbase, 128, q, t);
#pragma unroll
    for (int mi = 0; mi < 2; mi++)
#pragma unroll
        for (int nt = 0; nt < 8; nt++) {
            int rr = mbase + mi * 16 + q, cc = nbase + nt * 8 + 2 * t;
            float b0 = bias[cc], b1 = bias[cc + 1];
            *(float2*)&outp[(rowbase + rr) * 128 + cc] =
                make_float2(acc[mi][nt][0] + b0, acc[mi][nt][1] + b1);
            *(float2*)&outp[(rowbase + rr + 8) * 128 + cc] =
                make_float2(acc[mi][nt][2] + b0, acc[mi][nt][3] + b1);
        }
}

__global__ __launch_bounds__(256, 1)
void k_qkv_tc(const float* __restrict__ x,
              const float* __restrict__ latg, const float* __restrict__ latb,
              const float* __restrict__ bq, const float* __restrict__ bk,
              const float* __restrict__ bv) {
    extern __shared__ uint32_t sm[];
    uint32_t* As = sm;                   // 128*132
    uint32_t* B0 = As + 128 * 132;       // 128*136
    uint32_t* B1 = B0 + 128 * 136;       // 128*136
    float* sg = (float*)(B1 + 128 * 136);
    float* sb = sg + 128;
    const int tid = threadIdx.x;
    const size_t rowbase = (size_t)blockIdx.x * 128;

    cpy136(B0, gw_qkvo, 128, tid);          cp_commit();   // wq
    cpy136(B1, gw_qkvo + 16384, 128, tid);  cp_commit();   // wk

    if (tid < 128) { sg[tid] = latg[tid]; sb[tid] = latb[tid]; }
    const int r = tid >> 1, h = tid & 1;
    const float* xr = x + (rowbase + r) * 128 + h * 64;
    uint32_t* ar = As + r * 132 + h * 64;
    float s = 0.f, s2 = 0.f;
    for (int j = 0; j < 64; j += 4) {
        float4 v = *(const float4*)&xr[j];
        s += v.x + v.y + v.z + v.w;
        s2 += v.x * v.x + v.y * v.y + v.z * v.z + v.w * v.w;
        ar[j]     = __float_as_uint(v.x);
        ar[j + 1] = __float_as_uint(v.y);
        ar[j + 2] = __float_as_uint(v.z);
        ar[j + 3] = __float_as_uint(v.w);
    }
    s  += __shfl_xor_sync(0xffffffffu, s, 1);
    s2 += __shfl_xor_sync(0xffffffffu, s2, 1);
    float mu = s * (1.f / 128.f);
    float rs = rsqrtf(s2 * (1.f / 128.f) - mu * mu + 1e-5f);
    __syncthreads();   // sg/sb visible
    for (int j = 0; j < 64; j++) {
        float v = __uint_as_float(ar[j]);
        ar[j] = cvt_tf32((v - mu) * rs * sg[h * 64 + j] + sb[h * 64 + j]);
    }
    __syncthreads();       // As complete
    cp_wait<1>();          // wq arrived
    __syncthreads();

    const int w = tid >> 5, lane = tid & 31, q = lane >> 2, t = lane & 3;
    qkv_gemm_epi(As, B0, bq, g_q, rowbase, w, q, t);
    __syncthreads();                              // done reading B0
    cpy136(B0, gw_qkvo + 32768, 128, tid);        // wv
    cp_commit();
    cp_wait<1>();                                 // wk arrived
    __syncthreads();
    qkv_gemm_epi(As, B1, bk, g_k, rowbase, w, q, t);
    cp_wait<0>();                                 // wv arrived
    __syncthreads();
    qkv_gemm_epi(As, B0, bv, g_v, rowbase, w, q, t);
}

// ===========================================================================
// K2: attention.  grid 4096 (4 c-groups/block), 256 thr.
// ===========================================================================
__global__ __launch_bounds__(256, 4)
void k_attn() {
    extern __shared__ float asm_[];
    float* qs = asm_;                  // [32][132]
    float* ks = qs + 32 * 132;
    float* vs = ks + 32 * 132;
    float* sc = vs + 32 * 132;         // [4][8][8]
    const int tid = threadIdx.x;
    const size_t base = (size_t)blockIdx.x * 32;

    for (int i = tid; i < 1024; i += 256) {
        int rr = i >> 5, c4 = (i & 31) * 4;
        *(float4*)&qs[rr * 132 + c4] = *(const float4*)&g_q[(base + rr) * 128 + c4];
        *(float4*)&ks[rr * 132 + c4] = *(const float4*)&g_k[(base + rr) * 128 + c4];
        *(float4*)&vs[rr * 132 + c4] = *(const float4*)&g_v[(base + rr) * 128 + c4];
    }
    __syncthreads();
    {
        int gi = tid >> 6, p = tid & 63, c = p >> 3, e = p & 7;
        const float* qp = qs + (gi * 8 + c) * 132;
        const float* kp = ks + (gi * 8 + e) * 132;
        float s = 0.f;
#pragma unroll 8
        for (int d = 0; d < 128; d += 4) {
            float4 a = *(const float4*)&qp[d];
            float4 b = *(const float4*)&kp[d];
            s += a.x * b.x + a.y * b.y + a.z * b.z + a.w * b.w;
        }
        s *= 0.088388347648318447f;
        float m = s;
        m = fmaxf(m, __shfl_xor_sync(0xffffffffu, m, 1));
        m = fmaxf(m, __shfl_xor_sync(0xffffffffu, m, 2));
        m = fmaxf(m, __shfl_xor_sync(0xffffffffu, m, 4));
        float ex = expf(s - m);
        float sum = ex;
        sum += __shfl_xor_sync(0xffffffffu, sum, 1);
        sum += __shfl_xor_sync(0xffffffffu, sum, 2);
        sum += __shfl_xor_sync(0xffffffffu, sum, 4);
        sc[(gi * 8 + c) * 8 + e] = ex / sum;
    }
    __syncthreads();
    {
        int gi = tid >> 6, p = tid & 63, c = p >> 3, d0 = (p & 7) * 16;
        float a[8];
#pragma unroll
        for (int e = 0; e < 8; e++) a[e] = sc[(gi * 8 + c) * 8 + e];
#pragma unroll
        for (int jj = 0; jj < 4; jj++) {
            float4 o = make_float4(0.f, 0.f, 0.f, 0.f);
#pragma unroll
            for (int e = 0; e < 8; e++) {
                float4 v = *(const float4*)&vs[(gi * 8 + e) * 132 + d0 + jj * 4];
                o.x += a[e] * v.x; o.y += a[e] * v.y;
                o.z += a[e] * v.z; o.w += a[e] * v.w;
            }
            *(float4*)&g_o[(base + gi * 8 + c) * 128 + d0 + jj * 4] = o;
        }
    }
}

// ===========================================================================
// K3: x_attn = x + o @ wo + bo.  grid 1024, 256 thr.
// ===========================================================================
__global__ __launch_bounds__(256, 1)
void k_wo_tc(const float* __restrict__ x, const float* __restrict__ bo) {
    extern __shared__ uint32_t sm[];
    uint32_t* As = sm;
    uint32_t* Bs = As + 128 * 132;
    const int tid = threadIdx.x;
    const size_t rowbase = (size_t)blockIdx.x * 128;

    cpy136(Bs, gw_qkvo + 49152, 128, tid);
    cp_commit();
    for (int i = tid; i < 16384; i += 256)
        As[(i >> 7) * 132 + (i & 127)] = cvt_tf32(g_o[rowbase * 128 + i]);
    cp_wait<0>();
    __syncthreads();

    const int w = tid >> 5, lane = tid & 31, q = lane >> 2, t = lane & 3;
    const int mbase = (w >> 1) * 32, nbase = (w & 1) * 64;
    float acc[2][8][4];
    zero_acc(&acc[0][0][0], 64);
    gemm_32x64<132, 136>(acc, As, Bs, mbase, nbase, 128, q, t);
#pragma unroll
    for (int mi = 0; mi < 2; mi++)
#pragma unroll
        for (int nt = 0; nt < 8; nt++) {
            int rr = mbase + mi * 16 + q, cc = nbase + nt * 8 + 2 * t;
            float b0 = bo[cc], b1 = bo[cc + 1];
            size_t o0 = (rowbase + rr) * 128 + cc;
            size_t o1 = (rowbase + rr + 8) * 128 + cc;
            float2 x0 = *(const float2*)&x[o0];
            float2 x1 = *(const float2*)&x[o1];
            *(float2*)&g_xa[o0] = make_float2(x0.x + acc[mi][nt][0] + b0,
                                              x0.y + acc[mi][nt][1] + b1);
            *(float2*)&g_xa[o1] = make_float2(x1.x + acc[mi][nt][2] + b0,
                                              x1.y + acc[mi][nt][3] + b1);
        }
}

// ===========================================================================
// K4: per-group: z/enc, surprise+gate, z_hat/pred, gain, GLN*gain -> g_hh
// grid (16, 64), 256 thr.
// ===========================================================================
__global__ __launch_bounds__(256, 1)
void k_small_tc(const float* __restrict__ zhp,
                const float* __restrict__ lng, const float* __restrict__ lnb,
                const float* __restrict__ encb, const float* __restrict__ predb,
                const float* __restrict__ gainb, float* out) {
    extern __shared__ uint32_t sm[];
    uint32_t* As = sm;                  // [128][132]
    uint32_t* Zs = As + 128 * 132;      // [128][68]
    uint32_t* Ds = Zs + 128 * 68;       // [128][68]
    uint32_t* B0 = Ds + 128 * 68;       // 128*72 (enc) / 64*136 (gain)
    uint32_t* B1 = B0 + 128 * 72;       // 64*72 (pred)
    float* smu = (float*)(B1 + 64 * 72);
    float* srs = smu + 128;
    const int tid = threadIdx.x;
    const int g = blockIdx.y, p0 = blockIdx.x * 128;

    cpy72(B0, gw_enc + (size_t)g * 8192, 128, tid);  cp_commit();
    cpy72(B1, gw_pred + (size_t)g * 4096, 64, tid);  cp_commit();

    {   // load x_attn, stats, cvt store
        const int r = tid >> 1, h = tid & 1;
        const float* xr = g_xa + ((size_t)(p0 + r) * 64 + g) * 128 + h * 64;
        uint32_t* ar = As + r * 132 + h * 64;
        float s = 0.f, s2 = 0.f;
        for (int j = 0; j < 64; j += 4) {
            float4 v = *(const float4*)&xr[j];
            s += v.x + v.y + v.z + v.w;
            s2 += v.x * v.x + v.y * v.y + v.z * v.z + v.w * v.w;
            ar[j]     = cvt_tf32(v.x);
            ar[j + 1] = cvt_tf32(v.y);
            ar[j + 2] = cvt_tf32(v.z);
            ar[j + 3] = cvt_tf32(v.w);
        }
        s  += __shfl_xor_sync(0xffffffffu, s, 1);
        s2 += __shfl_xor_sync(0xffffffffu, s2, 1);
        float mu = s * (1.f / 128.f);
        if (h == 0) {
            smu[r] = mu;
            srs[r] = rsqrtf(s2 * (1.f / 128.f) - mu * mu + 1e-5f);
        }
    }
    cp_wait<1>();     // enc ready
    __syncthreads();

    const int w = tid >> 5, lane = tid & 31, q = lane >> 2, t = lane & 3;
    const int mbase = w * 16;

    {   // enc GEMM: z = x @ enc_w  (K=128, N=64)
        float acc[8][4];
        zero_acc(&acc[0][0], 32);
        gemm_16<132, 72, 8>(acc, As, B0, mbase, 128, q, t);
        float sl = 0.f, sh = 0.f;
#pragma unroll
        for (int nt = 0; nt < 8; nt++) {
            int cc = nt * 8 + 2 * t;
            int rlo = mbase + q, rhi = rlo + 8;
            float z0 = acc[nt][0] + encb[g * 64 + cc];
            float z1 = acc[nt][1] + encb[g * 64 + cc + 1];
            float z2 = acc[nt][2] + encb[g * 64 + cc];
            float z3 = acc[nt][3] + encb[g * 64 + cc + 1];
            size_t qlo = (size_t)(p0 + rlo) * 64 + g;
            size_t qhi = (size_t)(p0 + rhi) * 64 + g;
            *(float2*)&out[OFF_Z + qlo * 64 + cc] = make_float2(z0, z1);
            *(float2*)&out[OFF_Z + qhi * 64 + cc] = make_float2(z2, z3);
            float2 plo = *(const float2*)&zhp[qlo * 64 + cc];
            float2 phi = *(const float2*)&zhp[qhi * 64 + cc];
            float d0 = z0 - plo.x, d1 = z1 - plo.y;
            float d2 = z2 - phi.x, d3 = z3 - phi.y;
            Zs[rlo * 68 + cc]     = cvt_tf32(z0);
            Zs[rlo * 68 + cc + 1] = cvt_tf32(z1);
            Zs[rhi * 68 + cc]     = cvt_tf32(z2);
            Zs[rhi * 68 + cc + 1] = cvt_tf32(z3);
            Ds[rlo * 68 + cc]     = cvt_tf32(d0);
            Ds[rlo * 68 + cc + 1] = cvt_tf32(d1);
            Ds[rhi * 68 + cc]     = cvt_tf32(d2);
            Ds[rhi * 68 + cc + 1] = cvt_tf32(d3);
            sl += d0 * d0 + d1 * d1;
            sh += d2 * d2 + d3 * d3;
        }
        sl += __shfl_xor_sync(0xffffffffu, sl, 1);
        sl += __shfl_xor_sync(0xffffffffu, sl, 2);
        sh += __shfl_xor_sync(0xffffffffu, sh, 1);
        sh += __shfl_xor_sync(0xffffffffu, sh, 2);
        if (t == 0) {
            float splo = sqrtf(sl), sphi = sqrtf(sh);
            size_t qlo = (size_t)(p0 + mbase + q) * 64 + g;
            size_t qhi = (size_t)(p0 + mbase + q + 8) * 64 + g;
            out[OFF_S + qlo] = splo;
            out[OFF_G + qlo] = fminf(splo, 1.0f);
            out[OFF_S + qhi] = sphi;
            out[OFF_G + qhi] = fminf(sphi, 1.0f);
        }
    }
    __syncthreads();                               // Zs/Ds visible; B0 free
    cpy136(B0, gw_gain + (size_t)g * 8192, 64, tid);
    cp_commit();
    cp_wait<1>();                                  // pred ready
    __syncthreads();
    {   // pred GEMM: z_hat = z @ pred_w  (K=64, N=64)
        float acc[8][4];
        zero_acc(&acc[0][0], 32);
        gemm_16<68, 72, 8>(acc, Zs, B1, mbase, 64, q, t);
#pragma unroll
        for (int nt = 0; nt < 8; nt++) {
            int cc = nt * 8 + 2 * t;
            size_t qlo = (size_t)(p0 + mbase + q) * 64 + g;
            size_t qhi = (size_t)(p0 + mbase + q + 8) * 64 + g;
            float b0 = predb[g * 64 + cc], b1 = predb[g * 64 + cc + 1];
            *(float2*)&out[OFF_ZH + qlo * 64 + cc] =
                make_float2(acc[nt][0] + b0, acc[nt][1] + b1);
            *(float2*)&out[OFF_ZH + qhi * 64 + cc] =
                make_float2(acc[nt][2] + b0, acc[nt][3] + b1);
        }
    }
    cp_wait<0>();                                  // gain ready
    __syncthreads();
    {   // gain GEMM (K=64, N=128) + GLN epilogue -> g_hh
        float acc[16][4];
        zero_acc(&acc[0][0], 64);
        gemm_16<68, 136, 16>(acc, Ds, B0, mbase, 64, q, t);
        int rlo = mbase + q, rhi = rlo + 8;
        float mlo = smu[rlo], rslo = srs[rlo];
        float mhi = smu[rhi], rshi = srs[rhi];
#pragma unroll
        for (int nt = 0; nt < 16; nt++) {
            int cc = nt * 8 + 2 * t;
#pragma unroll
            for (int jj = 0; jj < 2; jj++) {
                int c = cc + jj;
                float lg = lng[(size_t)g * 128 + c], lb = lnb[(size_t)g * 128 + c];
                float gb = gainb[(size_t)g * 128 + c];
                float gn0 = 1.0f + 0.1f * tanhf(acc[nt][jj] + gb);
                float gn1 = 1.0f + 0.1f * tanhf(acc[nt][2 + jj] + gb);
                float x0 = __uint_as_float(As[rlo * 132 + c]);
                float x1 = __uint_as_float(As[rhi * 132 + c]);
                g_hh[((size_t)(p0 + rlo) * 64 + g) * 128 + c] =
                    ((x0 - mlo) * rslo * lg + lb) * gn0;
                g_hh[((size_t)(p0 + rhi) * 64 + g) * 128 + c] =
                    ((x1 - mhi) * rshi * lg + lb) * gn1;
            }
        }
    }
}

// ===========================================================================
// K5: MLP with 64-wide H chunks, double-buffered cp.async.  grid (16,64).
// ===========================================================================
__global__ __launch_bounds__(256, 1)
void k_mlp_tc(const float* __restrict__ upb, const float* __restrict__ dwb,
              float* out) {
    extern __shared__ uint32_t sm[];
    uint32_t* As = sm;                  // [128][132] hh
    uint32_t* Us = As + 128 * 132;      // [128][68] gelu chunk
    uint32_t* B0 = Us + 128 * 68;       // up chunk [128][72]
    uint32_t* B1 = B0 + 128 * 72;       // down chunk [64][136]
    const int tid = threadIdx.x;
    const int g = blockIdx.y, p0 = blockIdx.x * 128;

    cpy72(B0, gw_up + (size_t)g * 65536, 128, tid);    cp_commit();
    for (int i = tid; i < 16384; i += 256) {
        int m = i >> 7, k = i & 127;
        As[m * 132 + k] = cvt_tf32(g_hh[((size_t)(p0 + m) * 64 + g) * 128 + k]);
    }
    cpy136(B1, gw_down + (size_t)g * 65536, 64, tid);  cp_commit();
    cp_wait<1>();                       // up0 ready
    __syncthreads();

    const int w = tid >> 5, lane = tid & 31, q = lane >> 2, t = lane & 3;
    const int mbase = w * 16;
    float oacc[16][4];
    zero_acc(&oacc[0][0], 64);

    for (int ch = 0; ch < 8; ch++) {
        float uacc[8][4];
        zero_acc(&uacc[0][0], 32);
        gemm_16<132, 72, 8>(uacc, As, B0, mbase, 128, q, t);
#pragma unroll
        for (int nt = 0; nt < 8; nt++) {
            int cc = nt * 8 + 2 * t;
            int rlo = mbase + q, rhi = rlo + 8;
#pragma unroll
            for (int jj = 0; jj < 2; jj++) {
                float bb = upb[(size_t)g * 512 + ch * 64 + cc + jj];
                float u0 = uacc[nt][jj] + bb;
                float u1 = uacc[nt][2 + jj] + bb;
                u0 = 0.5f * u0 * (1.0f + erff(u0 * 0.70710678118654752f));
                u1 = 0.5f * u1 * (1.0f + erff(u1 * 0.70710678118654752f));
                Us[rlo * 68 + cc + jj] = cvt_tf32(u0);
                Us[rhi * 68 + cc + jj] = cvt_tf32(u1);
            }
        }
        __syncthreads();                 // Us visible; B0 reads done
        if (ch < 7) {
            cpy72(B0, gw_up + (size_t)g * 65536 + (ch + 1) * 8192, 128, tid);
            cp_commit();
            cp_wait<1>();                // down_ch ready
        } else {
            cp_wait<0>();
        }
        __syncthreads();
        gemm_16<68, 136, 16>(oacc, Us, B1, mbase, 64, q, t);
        if (ch < 7) {
            __syncthreads();             // B1 reads done
            cpy136(B1, gw_down + (size_t)g * 65536 + (ch + 1) * 8192, 64, tid);
            cp_commit();
            cp_wait<1>();                // up_{ch+1} ready
            __syncthreads();
        }
    }
#pragma unroll
    for (int nt = 0; nt < 16; nt++) {
        int cc = nt * 8 + 2 * t;
        int rlo = mbase + q, rhi = rlo + 8;
        float b0 = dwb[(size_t)g * 128 + cc], b1 = dwb[(size_t)g * 128 + cc + 1];
        size_t o0 = ((size_t)(p0 + rlo) * 64 + g) * 128 + cc;
        size_t o1 = ((size_t)(p0 + rhi) * 64 + g) * 128 + cc;
        float2 x0 = *(const float2*)&g_xa[o0];
        float2 x1 = *(const float2*)&g_xa[o1];
        *(float2*)&out[OFF_XOUT + o0] = make_float2(x0.x + oacc[nt][0] + b0,
                                                    x0.y + oacc[nt][1] + b1);
        *(float2*)&out[OFF_XOUT + o1] = make_float2(x1.x + oacc[nt][2] + b0,
                                                    x1.y + oacc[nt][3] + b1);
    }
}

// ===========================================================================
// K6: post projection + normalize + w_nov, double-buffered.  grid (16,64).
// ===========================================================================
__global__ __launch_bounds__(256, 1)
void k_post_tc(const float* __restrict__ pb, float* out) {
    extern __shared__ uint32_t sm[];
    uint32_t* As = sm;                  // [128][132]
    uint32_t* B0 = As + 128 * 132;      // [128][136]
    uint32_t* B1 = B0 + 128 * 136;      // [128][136]
    float* pr = (float*)(B1 + 128 * 136);   // [2][128]
    const int tid = threadIdx.x;
    const int g = blockIdx.y, p0 = blockIdx.x * 128;

    cpy136(B0, gw_post + (size_t)g * 65536, 128, tid);          cp_commit();
    cpy136(B1, gw_post + (size_t)g * 65536 + 16384, 128, tid);  cp_commit();
    for (int i = tid; i < 16384; i += 256) {
        int m = i >> 7, k = i & 127;
        As[m * 132 + k] = cvt_tf32(out[OFF_XOUT + ((size_t)(p0 + m) * 64 + g) * 128 + k]);
    }
    __syncthreads();
    if (tid < 128) {   // novelty -> w_nov (overlaps cp waits)
        const float* wl = gw_plast + g * 128;
        float s = 0.f;
        for (int k = 0; k < 128; k++)
            s += __uint_as_float(As[tid * 132 + k]) * wl[k];
        s += pb[(size_t)g * 513 + 512];
        out[OFF_WN + (size_t)(p0 + tid) * 64 + g] = 1.0f / (1.0f + expf(-s));
    }
    const int w = tid >> 5, lane = tid & 31, q = lane >> 2, t = lane & 3;
    const int mbase = (w >> 1) * 32, nbase = (w & 1) * 64, wc = w & 1;

    for (int ch = 0; ch < 4; ch++) {
        if (ch < 3) cp_wait<1>(); else cp_wait<0>();
        __syncthreads();
        uint32_t* Bs = (ch & 1) ? B1 : B0;
        float acc[2][8][4];
        zero_acc(&acc[0][0][0], 64);
        gemm_32x64<132, 136>(acc, As, Bs, mbase, nbase, 128, q, t);
#pragma unroll
        for (int mi = 0; mi < 2; mi++)
#pragma unroll
            for (int nt = 0; nt < 8; nt++) {
                int cc = nbase + nt * 8 + 2 * t;
                float b0 = pb[(size_t)g * 513 + ch * 128 + cc];
                float b1 = pb[(size_t)g * 513 + ch * 128 + cc + 1];
                acc[mi][nt][0] += b0; acc[mi][nt][1] += b1;
                acc[mi][nt][2] += b0; acc[mi][nt][3] += b1;
            }
        if (ch == 1 || ch == 3) {
            size_t off = (ch == 1) ? OFF_VP : OFF_VC;
#pragma unroll
            for (int mi = 0; mi < 2; mi++)
#pragma unroll
                for (int nt = 0; nt < 8; nt++) {
                    int rr = mbase + mi * 16 + q, cc = nbase + nt * 8 + 2 * t;
                    size_t o0 = off + ((size_t)(p0 + rr) * 64 + g) * 128 + cc;
                    size_t o1 = off + ((size_t)(p0 + rr + 8) * 64 + g) * 128 + cc;
                    *(float2*)&out[o0] = make_float2(acc[mi][nt][0], acc[mi][nt][1]);
                    *(float2*)&out[o1] = make_float2(acc[mi][nt][2], acc[mi][nt][3]);
                }
        } else {
            float sl[2] = {0.f, 0.f}, sh[2] = {0.f, 0.f};
#pragma unroll
            for (int mi = 0; mi < 2; mi++)
#pragma unroll
                for (int nt = 0; nt < 8; nt++) {
                    sl[mi] += acc[mi][nt][0] * acc[mi][nt][0] + acc[mi][nt][1] * acc[mi][nt][1];
                    sh[mi] += acc[mi][nt][2] * acc[mi][nt][2] + acc[mi][nt][3] * acc[mi][nt][3];
                }
#pragma unroll
            for (int mi = 0; mi < 2; mi++) {
                sl[mi] += __shfl_xor_sync(0xffffffffu, sl[mi], 1);
                sl[mi] += __shfl_xor_sync(0xffffffffu, sl[mi], 2);
                sh[mi] += __shfl_xor_sync(0xffffffffu, sh[mi], 1);
                sh[mi] += __shfl_xor_sync(0xffffffffu, sh[mi], 2);
            }
            if (t == 0) {
#pragma unroll
                for (int mi = 0; mi < 2; mi++) {
                    pr[wc * 128 + mbase + mi * 16 + q] = sl[mi];
                    pr[wc * 128 + mbase + mi * 16 + q + 8] = sh[mi];
                }
            }
            __syncthreads();
            size_t off = (ch == 0) ? OFF_KC : OFF_QN;
#pragma unroll
            for (int mi = 0; mi < 2; mi++)
#pragma unroll
                for (int nt = 0; nt < 8; nt++) {
                    int rr = mbase + mi * 16 + q, cc = nbase + nt * 8 + 2 * t;
                    float i0 = 1.0f / fmaxf(sqrtf(pr[rr] + pr[128 + rr]), 1e-6f);
                    float i1 = 1.0f / fmaxf(sqrtf(pr[rr + 8] + pr[128 + rr + 8]), 1e-6f);
                    size_t o0 = off + ((size_t)(p0 + rr) * 64 + g) * 128 + cc;
                    size_t o1 = off + ((size_t)(p0 + rr + 8) * 64 + g) * 128 + cc;
                    *(float2*)&out[o0] = make_float2(acc[mi][nt][0] * i0, acc[mi][nt][1] * i0);
                    *(float2*)&out[o1] = make_float2(acc[mi][nt][2] * i1, acc[mi][nt][3] * i1);
                }
        }
        if (ch < 2) {
            __syncthreads();             // buffer reads done
            cpy136((ch & 1) ? B1 : B0,
                   gw_post + (size_t)g * 65536 + (ch + 2) * 16384, 128, tid);
            cp_commit();
        }
    }
}

// ===========================================================================
extern "C" void kernel_launch(void* const* d_in, const int* in_sizes, int n_in,
                              void* d_out, int out_size) {
    const float* x_col  = (const float*)d_in[0];
    const float* zhp    = (const float*)d_in[1];
    const float* ln_g   = (const float*)d_in[2];
    const float* ln_b   = (const float*)d_in[3];
    const float* up_w   = (const float*)d_in[4];
    const float* up_b   = (const float*)d_in[5];
    const float* down_w = (const float*)d_in[6];
    const float* down_b = (const float*)d_in[7];
    const float* lat_g  = (const float*)d_in[8];
    const float* lat_b  = (const float*)d_in[9];
    const float* wq     = (const float*)d_in[10];
    const float* bq     = (const float*)d_in[11];
    const float* wk     = (const float*)d_in[12];
    const float* bk     = (const float*)d_in[13];
    const float* wv     = (const float*)d_in[14];
    const float* bv     = (const float*)d_in[15];
    const float* wo     = (const float*)d_in[16];
    const float* bo     = (const float*)d_in[17];
    const float* post_w = (const float*)d_in[18];
    const float* post_b = (const float*)d_in[19];
    const float* enc_w  = (const float*)d_in[20];
    const float* enc_b  = (const float*)d_in[21];
    const float* pred_w = (const float*)d_in[22];
    const float* pred_b = (const float*)d_in[23];
    const float* gain_w = (const float*)d_in[24];
    const float* gain_b = (const float*)d_in[25];
    float* out = (float*)d_out;

    const int SM_QKV   = (128 * 132 + 2 * 128 * 136 + 256) * 4;   // 207872
    const int SM_ATTN  = (3 * 32 * 132 + 256) * 4;                // 51712
    const int SM_WO    = (128 * 132 + 128 * 136) * 4;             // 137216
    const int SM_SMALL = (128 * 132 + 2 * 128 * 68 + 128 * 72 + 64 * 72 + 256) * 4;
    const int SM_MLP   = (128 * 132 + 128 * 68 + 128 * 72 + 64 * 136) * 4;
    const int SM_POST  = (128 * 132 + 2 * 128 * 136 + 256) * 4;

    cudaFuncSetAttribute(k_qkv_tc,   cudaFuncAttributeMaxDynamicSharedMemorySize, SM_QKV);
    cudaFuncSetAttribute(k_attn,     cudaFuncAttributeMaxDynamicSharedMemorySize, SM_ATTN);
    cudaFuncSetAttribute(k_wo_tc,    cudaFuncAttributeMaxDynamicSharedMemorySize, SM_WO);
    cudaFuncSetAttribute(k_small_tc, cudaFuncAttributeMaxDynamicSharedMemorySize, SM_SMALL);
    cudaFuncSetAttribute(k_mlp_tc,   cudaFuncAttributeMaxDynamicSharedMemorySize, SM_MLP);
    cudaFuncSetAttribute(k_post_tc,  cudaFuncAttributeMaxDynamicSharedMemorySize, SM_POST);

    // weight preparation
    k_cvt_qkvo <<<64,   256>>>(wq, wk, wv, wo);
    k_cvt_small<<<1024, 256>>>(enc_w, pred_w, gain_w);
    k_cvt_down <<<2048, 256>>>(down_w);
    k_cvt_up   <<<2048, 256>>>(up_w);
    k_cvt_post <<<2048, 256>>>(post_w);

    k_qkv_tc<<<R_TOT / 128, 256, SM_QKV>>>(x_col, lat_g, lat_b, bq, bk, bv);
    k_attn<<<R_TOT / 32, 256, SM_ATTN>>>();
    k_wo_tc<<<R_TOT / 128, 256, SM_WO>>>(x_col, bo);
    k_small_tc<<<dim3(TOKS / 128, 64), 256, SM_SMALL>>>(zhp, ln_g, ln_b,
                                                        enc_b, pred_b, gain_b, out);
    k_mlp_tc<<<dim3(TOKS / 128, 64), 256, SM_MLP>>>(up_b, down_b, out);
    k_post_tc<<<dim3(TOKS / 128, 64), 256, SM_POST>>>(post_b, out);
}

// round 5
// speedup vs baseline: 3.2811x; 1.1759x over previous
#include <cuda_runtime.h>
#include <math.h>
#include <stdint.h>

#define R_TOT 131072   // BS*N*G rows
#define TOKS  2048     // BS*N tokens

static constexpr size_t OFF_XOUT = 0;
static constexpr size_t OFF_Z    = 16777216;
static constexpr size_t OFF_ZH   = 25165824;
static constexpr size_t OFF_S    = 33554432;
static constexpr size_t OFF_KC   = 33685504;
static constexpr size_t OFF_VP   = 50462720;
static constexpr size_t OFF_G    = 67239936;
static constexpr size_t OFF_QN   = 67371008;
static constexpr size_t OFF_VC   = 84148224;
static constexpr size_t OFF_WN   = 100925440;

// Scratch
__device__ float g_xa[16777216];

// Pre-converted tf32 weights
__device__ uint32_t gw_qkvo[65536];       // wq,wk,wv,wo @ 0,16384,32768,49152
__device__ uint32_t gw_enc [524288];      // [g][128][64]
__device__ uint32_t gw_pred[262144];      // [g][64][64]
__device__ uint32_t gw_gain[524288];      // [g][64][128]
__device__ uint32_t gw_up  [4194304];     // [g][8ch][128k][64n]
__device__ uint32_t gw_down[4194304];     // [g][512][128]
__device__ uint32_t gw_post[4194304];     // [g][4ch][128k][128n]
__device__ float    gw_plast[8192];       // post_w last column [g][128]

// ===========================================================================
__device__ __forceinline__ uint32_t cvt_tf32(float f) {
    uint32_t r;
    asm("cvt.rna.tf32.f32 %0, %1;" : "=r"(r) : "f"(f));
    return r;
}
__device__ __forceinline__ void mma8(float* c, const uint32_t* a,
                                     uint32_t b0, uint32_t b1) {
    asm volatile(
        "mma.sync.aligned.m16n8k8.row.col.f32.tf32.tf32.f32 "
        "{%0,%1,%2,%3}, {%4,%5,%6,%7}, {%8,%9}, {%0,%1,%2,%3};"
        : "+f"(c[0]), "+f"(c[1]), "+f"(c[2]), "+f"(c[3])
        : "r"(a[0]), "r"(a[1]), "r"(a[2]), "r"(a[3]), "r"(b0), "r"(b1));
}
__device__ __forceinline__ void cp16(void* smem, const void* gmem) {
    uint32_t s = (uint32_t)__cvta_generic_to_shared(smem);
    asm volatile("cp.async.cg.shared.global [%0], [%1], 16;" :: "r"(s), "l"(gmem));
}
__device__ __forceinline__ void cp_commit() {
    asm volatile("cp.async.commit_group;" ::: "memory");
}
template<int N> __device__ __forceinline__ void cp_wait() {
    asm volatile("cp.async.wait_group %0;" :: "n"(N) : "memory");
}
__device__ __forceinline__ void cpy136(uint32_t* dst, const uint32_t* src,
                                       int rows, int tid) {
    for (int i = tid; i < rows * 32; i += 256) {
        int k = i >> 5, n = (i & 31) * 4;
        cp16(dst + k * 136 + n, src + k * 128 + n);
    }
}
__device__ __forceinline__ void cpy72(uint32_t* dst, const uint32_t* src,
                                      int rows, int tid) {
    for (int i = tid; i < rows * 16; i += 256) {
        int k = i >> 4, n = (i & 15) * 4;
        cp16(dst + k * 72 + n, src + k * 64 + n);
    }
}
// 16xN tile, full-N (no nbase)
template<int LDA, int LDB, int NT>
__device__ __forceinline__ void gemm_16(float acc[NT][4],
        const uint32_t* __restrict__ As, const uint32_t* __restrict__ Bs,
        int mbase, int K, int q, int t) {
#pragma unroll 2
    for (int kb = 0; kb < K; kb += 8) {
        uint32_t a[4];
        const uint32_t* ap = As + (mbase + q) * LDA + kb + t;
        a[0] = ap[0];
        a[1] = ap[8 * LDA];
        a[2] = ap[4];
        a[3] = ap[8 * LDA + 4];
#pragma unroll
        for (int nt = 0; nt < NT; nt++) {
            const uint32_t* bp = Bs + (kb + t) * LDB + nt * 8 + q;
            mma8(acc[nt], a, bp[0], bp[4 * LDB]);
        }
    }
}
// 16x64 tile at (mbase, nbase)
template<int LDA, int LDB>
__device__ __forceinline__ void gemm_16n(float acc[8][4],
        const uint32_t* __restrict__ As, const uint32_t* __restrict__ Bs,
        int mbase, int nbase, int K, int q, int t) {
#pragma unroll 2
    for (int kb = 0; kb < K; kb += 8) {
        uint32_t a[4];
        const uint32_t* ap = As + (mbase + q) * LDA + kb + t;
        a[0] = ap[0];
        a[1] = ap[8 * LDA];
        a[2] = ap[4];
        a[3] = ap[8 * LDA + 4];
#pragma unroll
        for (int nt = 0; nt < 8; nt++) {
            const uint32_t* bp = Bs + (kb + t) * LDB + nbase + nt * 8 + q;
            mma8(acc[nt], a, bp[0], bp[4 * LDB]);
        }
    }
}
__device__ __forceinline__ void zero_acc(float* a, int n) {
#pragma unroll
    for (int i = 0; i < n; i++) a[i] = 0.f;
}

// ===========================================================================
// Weight prep (single kernel)
// ===========================================================================
__global__ void k_cvt_all(const float* __restrict__ wq, const float* __restrict__ wk,
                          const float* __restrict__ wv, const float* __restrict__ wo,
                          const float* __restrict__ encw, const float* __restrict__ predw,
                          const float* __restrict__ gainw, const float* __restrict__ uw,
                          const float* __restrict__ dw, const float* __restrict__ pw) {
    int tid0 = blockIdx.x * 256 + threadIdx.x, st = gridDim.x * 256;
    for (int i = tid0; i < 65536; i += st) {
        int sel = i >> 14, j = i & 16383;
        const float* p = (sel == 0) ? wq : (sel == 1) ? wk : (sel == 2) ? wv : wo;
        gw_qkvo[i] = cvt_tf32(p[j]);
    }
    for (int i = tid0; i < 524288; i += st) gw_enc[i] = cvt_tf32(encw[i]);
    for (int i = tid0; i < 262144; i += st) gw_pred[i] = cvt_tf32(predw[i]);
    for (int i = tid0; i < 524288; i += st) gw_gain[i] = cvt_tf32(gainw[i]);
    for (int i = tid0; i < 4194304; i += st) gw_down[i] = cvt_tf32(dw[i]);
    for (int i = tid0; i < 4194304; i += st) {
        int g = i >> 16, ch = (i >> 13) & 7, k = (i >> 6) & 127, n = i & 63;
        gw_up[i] = cvt_tf32(uw[(size_t)(g * 128 + k) * 512 + ch * 64 + n]);
    }
    for (int i = tid0; i < 4194304; i += st) {
        int g = i >> 16, ch = (i >> 14) & 3, k = (i >> 7) & 127, n = i & 127;
        gw_post[i] = cvt_tf32(pw[(size_t)(g * 128 + k) * 513 + ch * 128 + n]);
    }
    for (int i = tid0; i < 8192; i += st)
        gw_plast[i] = pw[(size_t)i * 513 + 512];
}

// ===========================================================================
// K1: fused LN + QKV + attention + wo.  grid 2048 (64 rows), 256 thr.
// smem words: As[64*132] W0[128*136] QK[128*136] Qb[64*132] sc[512] sg/sb[256]
// ===========================================================================
__global__ __launch_bounds__(256, 1)
void k_fattn(const float* __restrict__ x,
             const float* __restrict__ latg, const float* __restrict__ latb,
             const float* __restrict__ bq, const float* __restrict__ bk,
             const float* __restrict__ bv, const float* __restrict__ bo) {
    extern __shared__ uint32_t sm[];
    uint32_t* As = sm;                       // 8448
    uint32_t* W0 = As + 8448;                // 17408
    uint32_t* QK = W0 + 17408;               // 17408: K at +8704, V at +0
    uint32_t* Qb = QK + 17408;               // 8448
    float* sc = (float*)(Qb + 8448);         // 512
    float* sg = sc + 512;                    // 128
    float* sb = sg + 128;                    // 128
    const int tid = threadIdx.x;
    const size_t rowbase = (size_t)blockIdx.x * 64;

    cpy136(W0, gw_qkvo, 128, tid);          cp_commit();  // wq
    cpy136(QK, gw_qkvo + 16384, 128, tid);  cp_commit();  // wk

    if (tid < 128) { sg[tid] = latg[tid]; sb[tid] = latb[tid]; }
    // load x + LN stats: 4 threads per row, 32 cols each
    const int r = tid >> 2, qt = tid & 3;
    {
        const float* xr = x + (rowbase + r) * 128 + qt * 32;
        uint32_t* ar = As + r * 132 + qt * 32;
        float s = 0.f, s2 = 0.f;
        for (int j = 0; j < 32; j += 4) {
            float4 v = *(const float4*)&xr[j];
            s += v.x + v.y + v.z + v.w;
            s2 += v.x * v.x + v.y * v.y + v.z * v.z + v.w * v.w;
            ar[j]     = __float_as_uint(v.x);
            ar[j + 1] = __float_as_uint(v.y);
            ar[j + 2] = __float_as_uint(v.z);
            ar[j + 3] = __float_as_uint(v.w);
        }
        s  += __shfl_xor_sync(0xffffffffu, s, 1);
        s  += __shfl_xor_sync(0xffffffffu, s, 2);
        s2 += __shfl_xor_sync(0xffffffffu, s2, 1);
        s2 += __shfl_xor_sync(0xffffffffu, s2, 2);
        float mu = s * (1.f / 128.f);
        float rs = rsqrtf(s2 * (1.f / 128.f) - mu * mu + 1e-5f);
        __syncthreads();   // sg/sb + all As writes
        for (int j = 0; j < 32; j++) {
            float v = __uint_as_float(ar[j]);
            ar[j] = cvt_tf32((v - mu) * rs * sg[qt * 32 + j] + sb[qt * 32 + j]);
        }
    }
    __syncthreads();       // As final
    cp_wait<1>();          // wq done
    __syncthreads();

    const int w = tid >> 5, lane = tid & 31, q = lane >> 2, t = lane & 3;
    const int mbase = (w >> 1) * 16, nbase = (w & 1) * 64;

    {   // Q gemm -> Qb (fp32, stride 132)
        float acc[8][4];
        zero_acc(&acc[0][0], 32);
        gemm_16n<132, 136>(acc, As, W0, mbase, nbase, 128, q, t);
#pragma unroll
        for (int nt = 0; nt < 8; nt++) {
            int rr = mbase + q, cc = nbase + nt * 8 + 2 * t;
            float b0 = bq[cc], b1 = bq[cc + 1];
            Qb[rr * 132 + cc]           = __float_as_uint(acc[nt][0] + b0);
            Qb[rr * 132 + cc + 1]       = __float_as_uint(acc[nt][1] + b1);
            Qb[(rr + 8) * 132 + cc]     = __float_as_uint(acc[nt][2] + b0);
            Qb[(rr + 8) * 132 + cc + 1] = __float_as_uint(acc[nt][3] + b1);
        }
    }
    __syncthreads();                            // W0 reads done
    cpy136(W0, gw_qkvo + 32768, 128, tid);      // wv
    cp_commit();
    cp_wait<1>();                               // wk done
    __syncthreads();
    {   // K gemm (B=QK holds wk) -> regs -> overwrite QK upper half
        float acc[8][4];
        zero_acc(&acc[0][0], 32);
        gemm_16n<132, 136>(acc, As, QK, mbase, nbase, 128, q, t);
        __syncthreads();                        // all reads of wk done
        uint32_t* Ks = QK + 8704;
#pragma unroll
        for (int nt = 0; nt < 8; nt++) {
            int rr = mbase + q, cc = nbase + nt * 8 + 2 * t;
            float b0 = bk[cc], b1 = bk[cc + 1];
            Ks[rr * 136 + cc]           = __float_as_uint(acc[nt][0] + b0);
            Ks[rr * 136 + cc + 1]       = __float_as_uint(acc[nt][1] + b1);
            Ks[(rr + 8) * 136 + cc]     = __float_as_uint(acc[nt][2] + b0);
            Ks[(rr + 8) * 136 + cc + 1] = __float_as_uint(acc[nt][3] + b1);
        }
    }
    __syncthreads();
    {   // scores: 512 (grp,c,e) pairs
        const float* Ks = (const float*)(QK + 8704);
#pragma unroll
        for (int i = 0; i < 2; i++) {
            int p = tid + 256 * i;
            int rowq = p >> 3;           // grp*8 + c
            int grp = p >> 6, e = p & 7;
            const float* qp = (const float*)Qb + rowq * 132;
            const float* kp = Ks + (grp * 8 + e) * 136;
            float s = 0.f;
#pragma unroll 8
            for (int d = 0; d < 128; d += 4) {
                float4 a = *(const float4*)&qp[d];
                float4 b = *(const float4*)&kp[d];
                s += a.x * b.x + a.y * b.y + a.z * b.z + a.w * b.w;
            }
            sc[p] = s * 0.088388347648318447f;
        }
    }
    __syncthreads();
    if (tid < 64) {    // softmax over e per (grp,c)
        float* row = sc + tid * 8;
        float m = row[0];
#pragma unroll
        for (int e = 1; e < 8; e++) m = fmaxf(m, row[e]);
        float ex[8], ssum = 0.f;
#pragma unroll
        for (int e = 0; e < 8; e++) { ex[e] = expf(row[e] - m); ssum += ex[e]; }
        float inv = 1.0f / ssum;
#pragma unroll
        for (int e = 0; e < 8; e++) row[e] = ex[e] * inv;
    }
    cp_wait<0>();                               // wv done
    __syncthreads();
    {   // V gemm (B=W0=wv) -> overwrite QK lower half (V values)
        float acc[8][4];
        zero_acc(&acc[0][0], 32);
        gemm_16n<132, 136>(acc, As, W0, mbase, nbase, 128, q, t);
        __syncthreads();                        // scores done reading? (yes) + Q/K free
        uint32_t* Vs = QK;
#pragma unroll
        for (int nt = 0; nt < 8; nt++) {
            int rr = mbase + q, cc = nbase + nt * 8 + 2 * t;
            float b0 = bv[cc], b1 = bv[cc + 1];
            Vs[rr * 136 + cc]           = __float_as_uint(acc[nt][0] + b0);
            Vs[rr * 136 + cc + 1]       = __float_as_uint(acc[nt][1] + b1);
            Vs[(rr + 8) * 136 + cc]     = __float_as_uint(acc[nt][2] + b0);
            Vs[(rr + 8) * 136 + cc + 1] = __float_as_uint(acc[nt][3] + b1);
        }
    }
    __syncthreads();                            // W0 (wv) reads done; Vs final
    cpy136(W0, gw_qkvo + 49152, 128, tid);      // wo
    cp_commit();
    {   // o = attn @ V  -> As (tf32), in place over h
        const float* Vs = (const float*)QK;
        int rr = tid >> 2, d0 = (tid & 3) * 32;
        int vb = (rr & ~7) * 136;
        float a[8];
#pragma unroll
        for (int e = 0; e < 8; e++) a[e] = sc[rr * 8 + e];
        for (int j = 0; j < 32; j += 4) {
            float4 o = make_float4(0.f, 0.f, 0.f, 0.f);
#pragma unroll
            for (int e = 0; e < 8; e++) {
                float4 v = *(const float4*)&Vs[vb + e * 136 + d0 + j];
                o.x += a[e] * v.x; o.y += a[e] * v.y;
                o.z += a[e] * v.z; o.w += a[e] * v.w;
            }
            As[rr * 132 + d0 + j]     = cvt_tf32(o.x);
            As[rr * 132 + d0 + j + 1] = cvt_tf32(o.y);
            As[rr * 132 + d0 + j + 2] = cvt_tf32(o.z);
            As[rr * 132 + d0 + j + 3] = cvt_tf32(o.w);
        }
    }
    cp_wait<0>();                               // wo done
    __syncthreads();                            // As(o) final
    {   // wo gemm + residual epilogue -> g_xa
        float acc[8][4];
        zero_acc(&acc[0][0], 32);
        gemm_16n<132, 136>(acc, As, W0, mbase, nbase, 128, q, t);
#pragma unroll
        for (int nt = 0; nt < 8; nt++) {
            int rr = mbase + q, cc = nbase + nt * 8 + 2 * t;
            float b0 = bo[cc], b1 = bo[cc + 1];
            size_t o0 = (rowbase + rr) * 128 + cc;
            size_t o1 = (rowbase + rr + 8) * 128 + cc;
            float2 x0 = *(const float2*)&x[o0];
            float2 x1 = *(const float2*)&x[o1];
            *(float2*)&g_xa[o0] = make_float2(x0.x + acc[nt][0] + b0,
                                              x0.y + acc[nt][1] + b1);
            *(float2*)&g_xa[o1] = make_float2(x1.x + acc[nt][2] + b0,
                                              x1.y + acc[nt][3] + b1);
        }
    }
}

// ===========================================================================
// K2: mega per-group kernel: small + MLP + post.  grid (16, 64), 256 thr.
// smem words: As 16896 | Zs 8704 | Ds 8704 | B0 9216 | B1 8704 | misc 512
// post overlays: B0p = Zs (17408 = Zs+Ds), B1p = B0 (17408 of B0+B1)
// ===========================================================================
__global__ __launch_bounds__(256, 1)
void k_mega(const float* __restrict__ zhp,
            const float* __restrict__ lng, const float* __restrict__ lnb,
            const float* __restrict__ encb, const float* __restrict__ predb,
            const float* __restrict__ gainb, const float* __restrict__ upb,
            const float* __restrict__ dwb, const float* __restrict__ pb,
            float* out) {
    extern __shared__ uint32_t sm[];
    uint32_t* As = sm;                  // 16896
    uint32_t* Zs = As + 16896;          // 8704  (later Us, later B0p lo)
    uint32_t* Ds = Zs + 8704;           // 8704  (later B0p hi)
    uint32_t* B0 = Ds + 8704;           // 9216  (enc, up; later B1p lo)
    uint32_t* B1 = B0 + 9216;           // 8704  (pred, gain, down; B1p hi)
    float* smu = (float*)(B1 + 8704);
    float* srs = smu + 128;
    float* pr  = srs + 128;             // 256
    uint32_t* B0p = Zs;
    uint32_t* B1p = B0;
    const int tid = threadIdx.x;
    const int g = blockIdx.y, p0 = blockIdx.x * 128;

    cpy72(B0, gw_enc + (size_t)g * 8192, 128, tid);  cp_commit();
    cpy72(B1, gw_pred + (size_t)g * 4096, 64, tid);  cp_commit();

    {   // As = tf32(x_attn), stats
        const int r = tid >> 1, h = tid & 1;
        const float* xr = g_xa + ((size_t)(p0 + r) * 64 + g) * 128 + h * 64;
        uint32_t* ar = As + r * 132 + h * 64;
        float s = 0.f, s2 = 0.f;
        for (int j = 0; j < 64; j += 4) {
            float4 v = *(const float4*)&xr[j];
            s += v.x + v.y + v.z + v.w;
            s2 += v.x * v.x + v.y * v.y + v.z * v.z + v.w * v.w;
            ar[j]     = cvt_tf32(v.x);
            ar[j + 1] = cvt_tf32(v.y);
            ar[j + 2] = cvt_tf32(v.z);
            ar[j + 3] = cvt_tf32(v.w);
        }
        s  += __shfl_xor_sync(0xffffffffu, s, 1);
        s2 += __shfl_xor_sync(0xffffffffu, s2, 1);
        float mu = s * (1.f / 128.f);
        if (h == 0) {
            smu[r] = mu;
            srs[r] = rsqrtf(s2 * (1.f / 128.f) - mu * mu + 1e-5f);
        }
    }
    cp_wait<1>();     // enc ready
    __syncthreads();

    const int w = tid >> 5, lane = tid & 31, q = lane >> 2, t = lane & 3;
    const int mbase = w * 16;

    {   // enc GEMM: z = x @ enc_w
        float acc[8][4];
        zero_acc(&acc[0][0], 32);
        gemm_16<132, 72, 8>(acc, As, B0, mbase, 128, q, t);
        float sl = 0.f, sh = 0.f;
#pragma unroll
        for (int nt = 0; nt < 8; nt++) {
            int cc = nt * 8 + 2 * t;
            int rlo = mbase + q, rhi = rlo + 8;
            float z0 = acc[nt][0] + encb[g * 64 + cc];
            float z1 = acc[nt][1] + encb[g * 64 + cc + 1];
            float z2 = acc[nt][2] + encb[g * 64 + cc];
            float z3 = acc[nt][3] + encb[g * 64 + cc + 1];
            size_t qlo = (size_t)(p0 + rlo) * 64 + g;
            size_t qhi = (size_t)(p0 + rhi) * 64 + g;
            *(float2*)&out[OFF_Z + qlo * 64 + cc] = make_float2(z0, z1);
            *(float2*)&out[OFF_Z + qhi * 64 + cc] = make_float2(z2, z3);
            float2 plo = *(const float2*)&zhp[qlo * 64 + cc];
            float2 phi = *(const float2*)&zhp[qhi * 64 + cc];
            float d0 = z0 - plo.x, d1 = z1 - plo.y;
            float d2 = z2 - phi.x, d3 = z3 - phi.y;
            Zs[rlo * 68 + cc]     = cvt_tf32(z0);
            Zs[rlo * 68 + cc + 1] = cvt_tf32(z1);
            Zs[rhi * 68 + cc]     = cvt_tf32(z2);
            Zs[rhi * 68 + cc + 1] = cvt_tf32(z3);
            Ds[rlo * 68 + cc]     = cvt_tf32(d0);
            Ds[rlo * 68 + cc + 1] = cvt_tf32(d1);
            Ds[rhi * 68 + cc]     = cvt_tf32(d2);
            Ds[rhi * 68 + cc + 1] = cvt_tf32(d3);
            sl += d0 * d0 + d1 * d1;
            sh += d2 * d2 + d3 * d3;
        }
        sl += __shfl_xor_sync(0xffffffffu, sl, 1);
        sl += __shfl_xor_sync(0xffffffffu, sl, 2);
        sh += __shfl_xor_sync(0xffffffffu, sh, 1);
        sh += __shfl_xor_sync(0xffffffffu, sh, 2);
        if (t == 0) {
            float splo = sqrtf(sl), sphi = sqrtf(sh);
            size_t qlo = (size_t)(p0 + mbase + q) * 64 + g;
            size_t qhi = (size_t)(p0 + mbase + q + 8) * 64 + g;
            out[OFF_S + qlo] = splo;
            out[OFF_G + qlo] = fminf(splo, 1.0f);
            out[OFF_S + qhi] = sphi;
            out[OFF_G + qhi] = fminf(sphi, 1.0f);
        }
    }
    __syncthreads();                                   // Zs/Ds visible; B0 free
    cpy72(B0, gw_up + (size_t)g * 65536, 128, tid);    cp_commit();   // up0
    cp_wait<1>();                                      // pred ready
    __syncthreads();
    {   // pred GEMM
        float acc[8][4];
        zero_acc(&acc[0][0], 32);
        gemm_16<68, 72, 8>(acc, Zs, B1, mbase, 64, q, t);
#pragma unroll
        for (int nt = 0; nt < 8; nt++) {
            int cc = nt * 8 + 2 * t;
            size_t qlo = (size_t)(p0 + mbase + q) * 64 + g;
            size_t qhi = (size_t)(p0 + mbase + q + 8) * 64 + g;
            float b0 = predb[g * 64 + cc], b1 = predb[g * 64 + cc + 1];
            *(float2*)&out[OFF_ZH + qlo * 64 + cc] =
                make_float2(acc[nt][0] + b0, acc[nt][1] + b1);
            *(float2*)&out[OFF_ZH + qhi * 64 + cc] =
                make_float2(acc[nt][2] + b0, acc[nt][3] + b1);
        }
    }
    __syncthreads();                                   // B1 free
    cpy136(B1, gw_gain + (size_t)g * 8192, 64, tid);   cp_commit();   // gain
    cp_wait<0>();                                      // up0 + gain ready
    __syncthreads();
    {   // gain GEMM + GLN epilogue -> As := tf32(hh) in place
        float acc[16][4];
        zero_acc(&acc[0][0], 64);
        gemm_16<68, 136, 16>(acc, Ds, B1, mbase, 64, q, t);
        int rlo = mbase + q, rhi = rlo + 8;
        float mlo = smu[rlo], rslo = srs[rlo];
        float mhi = smu[rhi], rshi = srs[rhi];
#pragma unroll
        for (int nt = 0; nt < 16; nt++) {
            int cc = nt * 8 + 2 * t;
#pragma unroll
            for (int jj = 0; jj < 2; jj++) {
                int c = cc + jj;
                float lg = lng[(size_t)g * 128 + c], lb = lnb[(size_t)g * 128 + c];
                float gb = gainb[(size_t)g * 128 + c];
                float gn0 = 1.0f + 0.1f * tanhf(acc[nt][jj] + gb);
                float gn1 = 1.0f + 0.1f * tanhf(acc[nt][2 + jj] + gb);
                float x0 = __uint_as_float(As[rlo * 132 + c]);
                float x1 = __uint_as_float(As[rhi * 132 + c]);
                As[rlo * 132 + c] = cvt_tf32(((x0 - mlo) * rslo * lg + lb) * gn0);
                As[rhi * 132 + c] = cvt_tf32(((x1 - mhi) * rshi * lg + lb) * gn1);
            }
        }
    }
    __syncthreads();                                   // As(hh); B1/Ds free
    cpy136(B1, gw_down + (size_t)g * 65536, 64, tid);  cp_commit();   // down0

    uint32_t* Us = Zs;
    float oacc[16][4];
    zero_acc(&oacc[0][0], 64);
    for (int ch = 0; ch < 8; ch++) {
        float uacc[8][4];
        zero_acc(&uacc[0][0], 32);
        gemm_16<132, 72, 8>(uacc, As, B0, mbase, 128, q, t);
#pragma unroll
        for (int nt = 0; nt < 8; nt++) {
            int cc = nt * 8 + 2 * t;
            int rlo = mbase + q, rhi = rlo + 8;
#pragma unroll
            for (int jj = 0; jj < 2; jj++) {
                float bb = upb[(size_t)g * 512 + ch * 64 + cc + jj];
                float u0 = uacc[nt][jj] + bb;
                float u1 = uacc[nt][2 + jj] + bb;
                u0 = 0.5f * u0 * (1.0f + erff(u0 * 0.70710678118654752f));
                u1 = 0.5f * u1 * (1.0f + erff(u1 * 0.70710678118654752f));
                Us[rlo * 68 + cc + jj] = cvt_tf32(u0);
                Us[rhi * 68 + cc + jj] = cvt_tf32(u1);
            }
        }
        __syncthreads();                 // Us visible; B0 reads done
        if (ch < 7) {
            cpy72(B0, gw_up + (size_t)g * 65536 + (ch + 1) * 8192, 128, tid);
            cp_commit();
            cp_wait<1>();                // down_ch ready
        } else {
            cp_wait<0>();
        }
        __syncthreads();
        gemm_16<68, 136, 16>(oacc, Us, B1, mbase, 64, q, t);
        if (ch < 7) {
            __syncthreads();             // B1 reads done
            cpy136(B1, gw_down + (size_t)g * 65536 + (ch + 1) * 8192, 64, tid);
            cp_commit();
            cp_wait<1>();                // up_{ch+1} ready
            __syncthreads();
        }
    }
    __syncthreads();                     // last down gemm reads of Us done
    {   // MLP epilogue: x_out = xa + mlp + b -> gmem AND As := tf32(x_out)
#pragma unroll
        for (int nt = 0; nt < 16; nt++) {
            int cc = nt * 8 + 2 * t;
            int rlo = mbase + q, rhi = rlo + 8;
            float b0 = dwb[(size_t)g * 128 + cc], b1 = dwb[(size_t)g * 128 + cc + 1];
            size_t o0 = ((size_t)(p0 + rlo) * 64 + g) * 128 + cc;
            size_t o1 = ((size_t)(p0 + rhi) * 64 + g) * 128 + cc;
            float2 x0 = *(const float2*)&g_xa[o0];
            float2 x1 = *(const float2*)&g_xa[o1];
            float v00 = x0.x + oacc[nt][0] + b0, v01 = x0.y + oacc[nt][1] + b1;
            float v10 = x1.x + oacc[nt][2] + b0, v11 = x1.y + oacc[nt][3] + b1;
            *(float2*)&out[OFF_XOUT + o0] = make_float2(v00, v01);
            *(float2*)&out[OFF_XOUT + o1] = make_float2(v10, v11);
            As[rlo * 132 + cc]     = cvt_tf32(v00);
            As[rlo * 132 + cc + 1] = cvt_tf32(v01);
            As[rhi * 132 + cc]     = cvt_tf32(v10);
            As[rhi * 132 + cc + 1] = cvt_tf32(v11);
        }
    }
    __syncthreads();                     // As(x_out); Zs/Ds/B0/B1 dead
    cpy136(B0p, gw_post + (size_t)g * 65536, 128, tid);          cp_commit();
    cpy136(B1p, gw_post + (size_t)g * 65536 + 16384, 128, tid);  cp_commit();

    if (tid < 128) {   // w_nov
        const float* wl = gw_plast + g * 128;
        float s = 0.f;
        for (int k = 0; k < 128; k++)
            s += __uint_as_float(As[tid * 132 + k]) * wl[k];
        s += pb[(size_t)g * 513 + 512];
        out[OFF_WN + (size_t)(p0 + tid) * 64 + g] = 1.0f / (1.0f + expf(-s));
    }
    const int mb2 = (w >> 1) * 32, nb2 = (w & 1) * 64, wc = w & 1;

    for (int ch = 0; ch < 4; ch++) {
        if (ch < 3) cp_wait<1>(); else cp_wait<0>();
        __syncthreads();
        uint32_t* Bs = (ch & 1) ? B1p : B0p;
        float acc[2][8][4];
        zero_acc(&acc[0][0][0], 64);
        gemm_16n<132, 136>(acc[0], As, Bs, mb2, nb2, 128, q, t);
        gemm_16n<132, 136>(acc[1], As, Bs, mb2 + 16, nb2, 128, q, t);
#pragma unroll
        for (int mi = 0; mi < 2; mi++)
#pragma unroll
            for (int nt = 0; nt < 8; nt++) {
                int cc = nb2 + nt * 8 + 2 * t;
                float b0 = pb[(size_t)g * 513 + ch * 128 + cc];
                float b1 = pb[(size_t)g * 513 + ch * 128 + cc + 1];
                acc[mi][nt][0] += b0; acc[mi][nt][1] += b1;
                acc[mi][nt][2] += b0; acc[mi][nt][3] += b1;
            }
        if (ch == 1 || ch == 3) {
            size_t off = (ch == 1) ? OFF_VP : OFF_VC;
#pragma unroll
            for (int mi = 0; mi < 2; mi++)
#pragma unroll
                for (int nt = 0; nt < 8; nt++) {
                    int rr = mb2 + mi * 16 + q, cc = nb2 + nt * 8 + 2 * t;
                    size_t o0 = off + ((size_t)(p0 + rr) * 64 + g) * 128 + cc;
                    size_t o1 = off + ((size_t)(p0 + rr + 8) * 64 + g) * 128 + cc;
                    *(float2*)&out[o0] = make_float2(acc[mi][nt][0], acc[mi][nt][1]);
                    *(float2*)&out[o1] = make_float2(acc[mi][nt][2], acc[mi][nt][3]);
                }
        } else {
            float sl[2] = {0.f, 0.f}, sh[2] = {0.f, 0.f};
#pragma unroll
            for (int mi = 0; mi < 2; mi++)
#pragma unroll
                for (int nt = 0; nt < 8; nt++) {
                    sl[mi] += acc[mi][nt][0] * acc[mi][nt][0] + acc[mi][nt][1] * acc[mi][nt][1];
                    sh[mi] += acc[mi][nt][2] * acc[mi][nt][2] + acc[mi][nt][3] * acc[mi][nt][3];
                }
#pragma unroll
            for (int mi = 0; mi < 2; mi++) {
                sl[mi] += __shfl_xor_sync(0xffffffffu, sl[mi], 1);
                sl[mi] += __shfl_xor_sync(0xffffffffu, sl[mi], 2);
                sh[mi] += __shfl_xor_sync(0xffffffffu, sh[mi], 1);
                sh[mi] += __shfl_xor_sync(0xffffffffu, sh[mi], 2);
            }
            if (t == 0) {
#pragma unroll
                for (int mi = 0; mi < 2; mi++) {
                    pr[wc * 128 + mb2 + mi * 16 + q] = sl[mi];
                    pr[wc * 128 + mb2 + mi * 16 + q + 8] = sh[mi];
                }
            }
            __syncthreads();
            size_t off = (ch == 0) ? OFF_KC : OFF_QN;
#pragma unroll
            for (int mi = 0; mi < 2; mi++)
#pragma unroll
                for (int nt = 0; nt < 8; nt++) {
                    int rr = mb2 + mi * 16 + q, cc = nb2 + nt * 8 + 2 * t;
                    float i0 = 1.0f / fmaxf(sqrtf(pr[rr] + pr[128 + rr]), 1e-6f);
                    float i1 = 1.0f / fmaxf(sqrtf(pr[rr + 8] + pr[128 + rr + 8]), 1e-6f);
                    size_t o0 = off + ((size_t)(p0 + rr) * 64 + g) * 128 + cc;
                    size_t o1 = off + ((size_t)(p0 + rr + 8) * 64 + g) * 128 + cc;
                    *(float2*)&out[o0] = make_float2(acc[mi][nt][0] * i0, acc[mi][nt][1] * i0);
                    *(float2*)&out[o1] = make_float2(acc[mi][nt][2] * i1, acc[mi][nt][3] * i1);
                }
        }
        if (ch < 2) {
            __syncthreads();
            cpy136((ch & 1) ? B1p : B0p,
                   gw_post + (size_t)g * 65536 + (ch + 2) * 16384, 128, tid);
            cp_commit();
        }
    }
}

// ===========================================================================
extern "C" void kernel_launch(void* const* d_in, const int* in_sizes, int n_in,
                              void* d_out, int out_size) {
    const float* x_col  = (const float*)d_in[0];
    const float* zhp    = (const float*)d_in[1];
    const float* ln_g   = (const float*)d_in[2];
    const float* ln_b   = (const float*)d_in[3];
    const float* up_w   = (const float*)d_in[4];
    const float* up_b   = (const float*)d_in[5];
    const float* down_w = (const float*)d_in[6];
    const float* down_b = (const float*)d_in[7];
    const float* lat_g  = (const float*)d_in[8];
    const float* lat_b  = (const float*)d_in[9];
    const float* wq     = (const float*)d_in[10];
    const float* bq     = (const float*)d_in[11];
    const float* wk     = (const float*)d_in[12];
    const float* bk     = (const float*)d_in[13];
    const float* wv     = (const float*)d_in[14];
    const float* bv     = (const float*)d_in[15];
    const float* wo     = (const float*)d_in[16];
    const float* bo     = (const float*)d_in[17];
    const float* post_w = (const float*)d_in[18];
    const float* post_b = (const float*)d_in[19];
    const float* enc_w  = (const float*)d_in[20];
    const float* enc_b  = (const float*)d_in[21];
    const float* pred_w = (const float*)d_in[22];
    const float* pred_b = (const float*)d_in[23];
    const float* gain_w = (const float*)d_in[24];
    const float* gain_b = (const float*)d_in[25];
    float* out = (float*)d_out;

    const int SM_FA   = (8448 + 17408 + 17408 + 8448 + 768) * 4;   // 209920
    const int SM_MEGA = (16896 + 8704 + 8704 + 9216 + 8704 + 512) * 4;  // 210944

    cudaFuncSetAttribute(k_fattn, cudaFuncAttributeMaxDynamicSharedMemorySize, SM_FA);
    cudaFuncSetAttribute(k_mega,  cudaFuncAttributeMaxDynamicSharedMemorySize, SM_MEGA);

    k_cvt_all<<<2048, 256>>>(wq, wk, wv, wo, enc_w, pred_w, gain_w,
                             up_w, down_w, post_w);
    k_fattn<<<R_TOT / 64, 256, SM_FA>>>(x_col, lat_g, lat_b, bq, bk, bv, bo);
    k_mega<<<dim3(TOKS / 128, 64), 256, SM_MEGA>>>(zhp, ln_g, ln_b,
                                                   enc_b, pred_b, gain_b,
                                                   up_b, down_b, post_b, out);
}